// round 3
// baseline (speedup 1.0000x reference)
#include <cuda_runtime.h>
#include <cstdint>

// ---------------------------------------------------------------------------
// Attention block: x[8,1024,1024] -> qkv -> 16-head softmax attn -> proj+bias
// All GEMMs on tensor cores via mma.sync m16n8k8 TF32 (fp32 accumulate).
// ---------------------------------------------------------------------------

constexpr int kDim   = 1024;
constexpr int kBatch = 8;
constexpr int kSeq   = 1024;
constexpr int kHeads = 16;
constexpr int kHd    = 64;
constexpr float kScale = 0.125f;   // 64^-0.5

// Scratch (allocation-free rule: __device__ globals)
__device__ float g_q[kBatch * kHeads * kSeq * kHd];
__device__ float g_k[kBatch * kHeads * kSeq * kHd];
__device__ float g_v[kBatch * kHeads * kSeq * kHd];
__device__ float g_att[kBatch * kSeq * kDim];

__device__ __forceinline__ unsigned f2tf(float x) {
    unsigned r;
    asm("cvt.rna.tf32.f32 %0, %1;" : "=r"(r) : "f"(x));
    return r;
}

__device__ __forceinline__ void mma_tf32(float* c, const unsigned* a, const unsigned* b) {
    asm volatile(
        "mma.sync.aligned.m16n8k8.row.col.f32.tf32.tf32.f32 "
        "{%0,%1,%2,%3}, {%4,%5,%6,%7}, {%8,%9}, {%0,%1,%2,%3};"
        : "+f"(c[0]), "+f"(c[1]), "+f"(c[2]), "+f"(c[3])
        : "r"(a[0]), "r"(a[1]), "r"(a[2]), "r"(a[3]), "r"(b[0]), "r"(b[1]));
}

__device__ __forceinline__ float qredmax(float v) {
    v = fmaxf(v, __shfl_xor_sync(0xffffffffu, v, 1));
    v = fmaxf(v, __shfl_xor_sync(0xffffffffu, v, 2));
    return v;
}
__device__ __forceinline__ float qredsum(float v) {
    v += __shfl_xor_sync(0xffffffffu, v, 1);
    v += __shfl_xor_sync(0xffffffffu, v, 2);
    return v;
}

// ---------------------------------------------------------------------------
// GEMM: C[m, f] = sum_c A[m, c] * Bm[f, c]   (both K-major => mma row.col)
// MODE 0: A = x, Bm = w_qkv (N=3072), epilogue scatters into g_q/g_k/g_v
// MODE 1: A = g_att, Bm = w_proj (N=1024), epilogue adds bias, writes C
// Tiles: 128x128x32, 256 threads (8 warps as 4Mx2N), register prefetch.
// ---------------------------------------------------------------------------
template <int MODE>
__global__ __launch_bounds__(256)
void gemm_tf32_kernel(const float* __restrict__ A, const float* __restrict__ Bm,
                      const float* __restrict__ bias, float* __restrict__ C) {
    __shared__ float sA[128][36];  // pad 4: fragment reads hit 32 distinct banks
    __shared__ float sB[128][36];

    const int tid  = threadIdx.x;
    const int m0   = blockIdx.y * 128;
    const int n0   = blockIdx.x * 128;
    const int warp = tid >> 5, lane = tid & 31;
    const int wm   = warp & 3, wn = warp >> 2;   // warp tile: 32(M) x 64(N)
    const int tg   = lane >> 2, tl = lane & 3;

    const float* Ap = (MODE == 0) ? A : (const float*)g_att;

    float acc[2][8][4];
#pragma unroll
    for (int mt = 0; mt < 2; mt++)
#pragma unroll
        for (int nt = 0; nt < 8; nt++)
#pragma unroll
            for (int i = 0; i < 4; i++) acc[mt][nt][i] = 0.f;

    const int lr = tid >> 3;          // 0..31
    const int lc = (tid & 7) << 2;    // 0..28 (float4 col)
    const float* pa = Ap + (m0 + lr) * kDim + lc;
    const float* pb = Bm + (n0 + lr) * kDim + lc;

    float4 ra[4], rb[4];
#pragma unroll
    for (int i = 0; i < 4; i++) {
        ra[i] = *(const float4*)(pa + i * 32 * kDim);
        rb[i] = *(const float4*)(pb + i * 32 * kDim);
    }

    for (int kt = 0; kt < kDim / 32; kt++) {
#pragma unroll
        for (int i = 0; i < 4; i++) {
            *(float4*)&sA[lr + i * 32][lc] = ra[i];
            *(float4*)&sB[lr + i * 32][lc] = rb[i];
        }
        __syncthreads();
        if (kt + 1 < kDim / 32) {   // prefetch next tile into regs (overlaps MMA)
            const float* qa = pa + (kt + 1) * 32;
            const float* qb = pb + (kt + 1) * 32;
#pragma unroll
            for (int i = 0; i < 4; i++) {
                ra[i] = *(const float4*)(qa + i * 32 * kDim);
                rb[i] = *(const float4*)(qb + i * 32 * kDim);
            }
        }
#pragma unroll
        for (int ks = 0; ks < 4; ks++) {
            unsigned af[2][4], bf[8][2];
#pragma unroll
            for (int mt = 0; mt < 2; mt++) {
                int r = wm * 32 + mt * 16 + tg;
                af[mt][0] = f2tf(sA[r    ][ks * 8 + tl    ]);
                af[mt][1] = f2tf(sA[r + 8][ks * 8 + tl    ]);
                af[mt][2] = f2tf(sA[r    ][ks * 8 + tl + 4]);
                af[mt][3] = f2tf(sA[r + 8][ks * 8 + tl + 4]);
            }
#pragma unroll
            for (int nt = 0; nt < 8; nt++) {
                int cc = wn * 64 + nt * 8 + tg;
                bf[nt][0] = f2tf(sB[cc][ks * 8 + tl    ]);
                bf[nt][1] = f2tf(sB[cc][ks * 8 + tl + 4]);
            }
#pragma unroll
            for (int mt = 0; mt < 2; mt++)
#pragma unroll
                for (int nt = 0; nt < 8; nt++)
                    mma_tf32(acc[mt][nt], af[mt], bf[nt]);
        }
        __syncthreads();
    }

#pragma unroll
    for (int mt = 0; mt < 2; mt++) {
        const int mLo = m0 + wm * 32 + mt * 16 + tg;
        const int mHi = mLo + 8;
#pragma unroll
        for (int nt = 0; nt < 8; nt++) {
            const int f = n0 + wn * 64 + nt * 8 + 2 * tl;
            if (MODE == 0) {
                // f = which*1024 + h*64 + d   (qkv.reshape(b,n,3,h,d))
                const int which = f >> 10;
                const int hh    = (f >> 6) & 15;
                const int dd    = f & 63;
                float* dst = (which == 0) ? g_q : ((which == 1) ? g_k : g_v);
                {
                    int bb = mLo >> 10, nn = mLo & 1023;
                    int idx = ((bb * kHeads + hh) * kSeq + nn) * kHd + dd;
                    *(float2*)(dst + idx) = make_float2(acc[mt][nt][0], acc[mt][nt][1]);
                }
                {
                    int bb = mHi >> 10, nn = mHi & 1023;
                    int idx = ((bb * kHeads + hh) * kSeq + nn) * kHd + dd;
                    *(float2*)(dst + idx) = make_float2(acc[mt][nt][2], acc[mt][nt][3]);
                }
            } else {
                const float b0v = bias[f], b1v = bias[f + 1];
                *(float2*)(C + mLo * kDim + f) =
                    make_float2(acc[mt][nt][0] + b0v, acc[mt][nt][1] + b1v);
                *(float2*)(C + mHi * kDim + f) =
                    make_float2(acc[mt][nt][2] + b0v, acc[mt][nt][3] + b1v);
            }
        }
    }
}

// ---------------------------------------------------------------------------
// Flash attention: CTA = (b, h, 64 q-rows). 4 warps x 16 rows. d=64.
// Per KV tile (64): S = (Q*scale)·K^T (TF32 mma), online softmax in regs,
// P staged through smem (reuses K region), O += P·V (TF32 mma).
// ---------------------------------------------------------------------------
__global__ __launch_bounds__(128)
void attn_kernel() {
    __shared__ float sKP[64][68];   // K tile / P tile / Q staging (stride%32==4)
    __shared__ float sV[64][72];    // V tile                     (stride%32==8)

    const int bx = blockIdx.x;
    const int qt = bx & 15;
    const int bh = bx >> 4;
    const int bb = bh >> 4;
    const int hh = bh & 15;
    const int tid = threadIdx.x, warp = tid >> 5, lane = tid & 31;
    const int tg = lane >> 2, tl = lane & 3;

    const float* Qp = g_q + (bb * kHeads + hh) * kSeq * kHd;
    const float* Kp = g_k + (bb * kHeads + hh) * kSeq * kHd;
    const float* Vp = g_v + (bb * kHeads + hh) * kSeq * kHd;
    const int q0 = qt * 64;

    const int lr = tid >> 4;         // 0..7
    const int lc = (tid & 15) << 2;  // 0..60

    // Stage Q through smem, pick up A-fragments for all 8 k-steps (pre-scaled)
#pragma unroll
    for (int i = 0; i < 8; i++) {
        int row = lr + i * 8;
        *(float4*)&sKP[row][lc] = *(const float4*)&Qp[(q0 + row) * kHd + lc];
    }
    __syncthreads();

    unsigned qf[8][4];
    {
        const int r = warp * 16 + tg;
#pragma unroll
        for (int ks = 0; ks < 8; ks++) {
            qf[ks][0] = f2tf(sKP[r    ][ks * 8 + tl    ] * kScale);
            qf[ks][1] = f2tf(sKP[r + 8][ks * 8 + tl    ] * kScale);
            qf[ks][2] = f2tf(sKP[r    ][ks * 8 + tl + 4] * kScale);
            qf[ks][3] = f2tf(sKP[r + 8][ks * 8 + tl + 4] * kScale);
        }
    }
    __syncthreads();

    float o[8][4];
#pragma unroll
    for (int nt = 0; nt < 8; nt++)
#pragma unroll
        for (int i = 0; i < 4; i++) o[nt][i] = 0.f;
    float mrun0 = -1e30f, mrun1 = -1e30f, lrun0 = 0.f, lrun1 = 0.f;

    for (int t = 0; t < 16; t++) {
#pragma unroll
        for (int i = 0; i < 8; i++) {
            int row = lr + i * 8;
            *(float4*)&sKP[row][lc] = *(const float4*)&Kp[(t * 64 + row) * kHd + lc];
            *(float4*)&sV [row][lc] = *(const float4*)&Vp[(t * 64 + row) * kHd + lc];
        }
        __syncthreads();

        // S = Q K^T  (N dim = kv index)
        float s[8][4];
#pragma unroll
        for (int nt = 0; nt < 8; nt++)
#pragma unroll
            for (int i = 0; i < 4; i++) s[nt][i] = 0.f;

#pragma unroll
        for (int ks = 0; ks < 8; ks++) {
            unsigned bfr[8][2];
#pragma unroll
            for (int nt = 0; nt < 8; nt++) {
                bfr[nt][0] = f2tf(sKP[nt * 8 + tg][ks * 8 + tl    ]);
                bfr[nt][1] = f2tf(sKP[nt * 8 + tg][ks * 8 + tl + 4]);
            }
#pragma unroll
            for (int nt = 0; nt < 8; nt++) mma_tf32(s[nt], qf[ks], bfr[nt]);
        }

        // Online softmax (rows r=tg and r=tg+8 per thread; quad covers cols)
        float mt0 = -1e30f, mt1 = -1e30f;
#pragma unroll
        for (int nt = 0; nt < 8; nt++) {
            mt0 = fmaxf(mt0, fmaxf(s[nt][0], s[nt][1]));
            mt1 = fmaxf(mt1, fmaxf(s[nt][2], s[nt][3]));
        }
        mt0 = qredmax(mt0);
        mt1 = qredmax(mt1);
        const float mn0 = fmaxf(mrun0, mt0), mn1 = fmaxf(mrun1, mt1);
        const float a0 = __expf(mrun0 - mn0), a1 = __expf(mrun1 - mn1);
        float sum0 = 0.f, sum1 = 0.f;
#pragma unroll
        for (int nt = 0; nt < 8; nt++) {
            s[nt][0] = __expf(s[nt][0] - mn0); sum0 += s[nt][0];
            s[nt][1] = __expf(s[nt][1] - mn0); sum0 += s[nt][1];
            s[nt][2] = __expf(s[nt][2] - mn1); sum1 += s[nt][2];
            s[nt][3] = __expf(s[nt][3] - mn1); sum1 += s[nt][3];
        }
        sum0 = qredsum(sum0);
        sum1 = qredsum(sum1);
        lrun0 = lrun0 * a0 + sum0;
        lrun1 = lrun1 * a1 + sum1;
        mrun0 = mn0;
        mrun1 = mn1;
#pragma unroll
        for (int nt = 0; nt < 8; nt++) {
            o[nt][0] *= a0; o[nt][1] *= a0; o[nt][2] *= a1; o[nt][3] *= a1;
        }

        __syncthreads();  // everyone done reading K from sKP

        // Route P through smem (own 16 rows -> A fragments), then O += P V
        const int pr = warp * 16 + tg;
#pragma unroll
        for (int nt = 0; nt < 8; nt++) {
            *(float2*)&sKP[pr    ][nt * 8 + 2 * tl] = make_float2(s[nt][0], s[nt][1]);
            *(float2*)&sKP[pr + 8][nt * 8 + 2 * tl] = make_float2(s[nt][2], s[nt][3]);
        }
        __syncwarp();

#pragma unroll
        for (int ks = 0; ks < 8; ks++) {   // K dim = kv index j
            unsigned pf[4];
            pf[0] = f2tf(sKP[pr    ][ks * 8 + tl    ]);
            pf[1] = f2tf(sKP[pr + 8][ks * 8 + tl    ]);
            pf[2] = f2tf(sKP[pr    ][ks * 8 + tl + 4]);
            pf[3] = f2tf(sKP[pr + 8][ks * 8 + tl + 4]);
            unsigned vfr[8][2];
#pragma unroll
            for (int nt = 0; nt < 8; nt++) {   // N dim = d
                vfr[nt][0] = f2tf(sV[ks * 8 + tl    ][nt * 8 + tg]);
                vfr[nt][1] = f2tf(sV[ks * 8 + tl + 4][nt * 8 + tg]);
            }
#pragma unroll
            for (int nt = 0; nt < 8; nt++) mma_tf32(o[nt], pf, vfr[nt]);
        }
        __syncthreads();  // before next tile overwrites sKP/sV
    }

    // Epilogue: normalize, write att as [b, n, h*64+d] so proj reads row-major
    const float inv0 = 1.f / lrun0, inv1 = 1.f / lrun1;
    const int r0 = q0 + warp * 16 + tg;
    const int r1 = r0 + 8;
#pragma unroll
    for (int nt = 0; nt < 8; nt++) {
        const int dd = nt * 8 + 2 * tl;
        *(float2*)&g_att[(bb * kSeq + r0) * kDim + hh * kHd + dd] =
            make_float2(o[nt][0] * inv0, o[nt][1] * inv0);
        *(float2*)&g_att[(bb * kSeq + r1) * kDim + hh * kHd + dd] =
            make_float2(o[nt][2] * inv1, o[nt][3] * inv1);
    }
}

// ---------------------------------------------------------------------------
extern "C" void kernel_launch(void* const* d_in, const int* in_sizes, int n_in,
                              void* d_out, int out_size) {
    (void)in_sizes; (void)n_in; (void)out_size;
    const float* x      = (const float*)d_in[0];
    const float* w_qkv  = (const float*)d_in[1];
    const float* w_proj = (const float*)d_in[2];
    const float* b_proj = (const float*)d_in[3];
    float* out = (float*)d_out;

    // 1) QKV projection (M=8192, N=3072, K=1024) -> scatter to q/k/v
    gemm_tf32_kernel<0><<<dim3(3 * kDim / 128, kBatch * kSeq / 128), 256>>>(
        x, w_qkv, nullptr, nullptr);

    // 2) Flash attention per (b, h, 64-row q tile)
    attn_kernel<<<kBatch * kHeads * (kSeq / 64), 128>>>();

    // 3) Output projection + bias (M=8192, N=1024, K=1024)
    gemm_tf32_kernel<1><<<dim3(kDim / 128, kBatch * kSeq / 128), 256>>>(
        nullptr, w_proj, b_proj, out);
}

// round 4
// speedup vs baseline: 1.4997x; 1.4997x over previous
#include <cuda_runtime.h>
#include <cuda_fp16.h>
#include <cstdint>

// ---------------------------------------------------------------------------
// Attention block: x[8,1024,1024] -> qkv -> 16-head softmax attn -> proj+bias
// All GEMMs: mma.sync m16n8k16 FP16 inputs, FP32 accumulate.
// Q/K/V/att scratch kept in fp16 (same 10-bit mantissa as the tf32 baseline
// which measured rel_err 6.7e-4; all accumulation stays fp32).
// ---------------------------------------------------------------------------

constexpr int kDim   = 1024;
constexpr int kBatch = 8;
constexpr int kSeq   = 1024;
constexpr int kHeads = 16;
constexpr int kHd    = 64;

// Scratch (allocation-free rule: __device__ globals), fp16.
__device__ __half g_q[kBatch * kHeads * kSeq * kHd];
__device__ __half g_k[kBatch * kHeads * kSeq * kHd];
__device__ __half g_v[kBatch * kHeads * kSeq * kHd];
__device__ __half g_att[kBatch * kSeq * kDim];

__device__ __forceinline__ void mma_fp16(float* c, const unsigned* a, const unsigned* b) {
    asm volatile(
        "mma.sync.aligned.m16n8k16.row.col.f32.f16.f16.f32 "
        "{%0,%1,%2,%3}, {%4,%5,%6,%7}, {%8,%9}, {%0,%1,%2,%3};"
        : "+f"(c[0]), "+f"(c[1]), "+f"(c[2]), "+f"(c[3])
        : "r"(a[0]), "r"(a[1]), "r"(a[2]), "r"(a[3]), "r"(b[0]), "r"(b[1]));
}

__device__ __forceinline__ unsigned h2u(float a, float b) {
    __half2 h = __floats2half2_rn(a, b);
    return *reinterpret_cast<unsigned*>(&h);
}

__device__ __forceinline__ float qredmax(float v) {
    v = fmaxf(v, __shfl_xor_sync(0xffffffffu, v, 1));
    v = fmaxf(v, __shfl_xor_sync(0xffffffffu, v, 2));
    return v;
}
__device__ __forceinline__ float qredsum(float v) {
    v += __shfl_xor_sync(0xffffffffu, v, 1);
    v += __shfl_xor_sync(0xffffffffu, v, 2);
    return v;
}

// ---------------------------------------------------------------------------
// GEMM: C[m, f] = sum_c A[m, c] * Bm[f, c]   (both K-major => mma row.col)
// MODE 0: A = x (f32), Bm = w_qkv (N=3072), scatter half results to g_q/k/v
// MODE 1: A = g_att (half), Bm = w_proj (N=1024), bias add, f32 out
// Tiles: 128x128x32, 256 threads (8 warps as 4Mx2N), register prefetch.
// smem rows padded to 40 halves (80B): fragment 8-rows x 4-words pattern maps
// to bank starts {0,20,8,28,16,4,24,12}+0..3 -> all 32 banks, conflict-free.
// ---------------------------------------------------------------------------
template <int MODE>
__global__ __launch_bounds__(256)
void gemm_fp16_kernel(const float* __restrict__ A, const float* __restrict__ Bm,
                      const float* __restrict__ bias, float* __restrict__ C) {
    __shared__ __half sA[128][40];
    __shared__ __half sB[128][40];

    const int tid  = threadIdx.x;
    const int m0   = blockIdx.y * 128;
    const int n0   = blockIdx.x * 128;
    const int warp = tid >> 5, lane = tid & 31;
    const int wm   = warp & 3, wn = warp >> 2;   // warp tile: 32(M) x 64(N)
    const int tg   = lane >> 2, tl = lane & 3;

    float acc[2][8][4];
#pragma unroll
    for (int mt = 0; mt < 2; mt++)
#pragma unroll
        for (int nt = 0; nt < 8; nt++)
#pragma unroll
            for (int i = 0; i < 4; i++) acc[mt][nt][i] = 0.f;

    // Loader: thread covers row lr (0..127), 16 halves starting at c0
    const int lr = tid >> 1;
    const int c0 = (tid & 1) * 16;

    const float*  pa4 = A + (m0 + lr) * kDim + c0;                     // MODE 0
    const __half* pah = g_att + (size_t)(m0 + lr) * kDim + c0;         // MODE 1
    const float*  pb4 = Bm + (n0 + lr) * kDim + c0;

    float4 ra[4], rb[4];
    uint4  ha[2];
    if (MODE == 0) {
#pragma unroll
        for (int j = 0; j < 4; j++) ra[j] = *(const float4*)(pa4 + 4 * j);
    } else {
#pragma unroll
        for (int j = 0; j < 2; j++) ha[j] = *(const uint4*)(pah + 8 * j);
    }
#pragma unroll
    for (int j = 0; j < 4; j++) rb[j] = *(const float4*)(pb4 + 4 * j);

    for (int kt = 0; kt < kDim / 32; kt++) {
        if (MODE == 0) {
#pragma unroll
            for (int j = 0; j < 4; j++) {
                uint2 u;
                u.x = h2u(ra[j].x, ra[j].y);
                u.y = h2u(ra[j].z, ra[j].w);
                *(uint2*)&sA[lr][c0 + 4 * j] = u;
            }
        } else {
            *(uint4*)&sA[lr][c0]     = ha[0];
            *(uint4*)&sA[lr][c0 + 8] = ha[1];
        }
#pragma unroll
        for (int j = 0; j < 4; j++) {
            uint2 u;
            u.x = h2u(rb[j].x, rb[j].y);
            u.y = h2u(rb[j].z, rb[j].w);
            *(uint2*)&sB[lr][c0 + 4 * j] = u;
        }
        __syncthreads();

        if (kt + 1 < kDim / 32) {     // prefetch next tile into regs
            const int off = (kt + 1) * 32;
            if (MODE == 0) {
#pragma unroll
                for (int j = 0; j < 4; j++) ra[j] = *(const float4*)(pa4 + off + 4 * j);
            } else {
#pragma unroll
                for (int j = 0; j < 2; j++) ha[j] = *(const uint4*)(pah + off + 8 * j);
            }
#pragma unroll
            for (int j = 0; j < 4; j++) rb[j] = *(const float4*)(pb4 + off + 4 * j);
        }

#pragma unroll
        for (int ks = 0; ks < 2; ks++) {
            unsigned af[2][4], bf[8][2];
#pragma unroll
            for (int mt = 0; mt < 2; mt++) {
                const int r = wm * 32 + mt * 16 + tg;
                af[mt][0] = *(const unsigned*)&sA[r    ][ks * 16 + 2 * tl    ];
                af[mt][1] = *(const unsigned*)&sA[r + 8][ks * 16 + 2 * tl    ];
                af[mt][2] = *(const unsigned*)&sA[r    ][ks * 16 + 2 * tl + 8];
                af[mt][3] = *(const unsigned*)&sA[r + 8][ks * 16 + 2 * tl + 8];
            }
#pragma unroll
            for (int nt = 0; nt < 8; nt++) {
                const int cc = wn * 64 + nt * 8 + tg;
                bf[nt][0] = *(const unsigned*)&sB[cc][ks * 16 + 2 * tl    ];
                bf[nt][1] = *(const unsigned*)&sB[cc][ks * 16 + 2 * tl + 8];
            }
#pragma unroll
            for (int mt = 0; mt < 2; mt++)
#pragma unroll
                for (int nt = 0; nt < 8; nt++)
                    mma_fp16(acc[mt][nt], af[mt], bf[nt]);
        }
        __syncthreads();
    }

#pragma unroll
    for (int mt = 0; mt < 2; mt++) {
        const int mLo = m0 + wm * 32 + mt * 16 + tg;
        const int mHi = mLo + 8;
#pragma unroll
        for (int nt = 0; nt < 8; nt++) {
            const int f = n0 + wn * 64 + nt * 8 + 2 * tl;
            if (MODE == 0) {
                // f = which*1024 + h*64 + d   (qkv.reshape(b,n,3,h,d))
                const int which = f >> 10;
                const int hh    = (f >> 6) & 15;
                const int dd    = f & 63;
                __half* dst = (which == 0) ? g_q : ((which == 1) ? g_k : g_v);
                {
                    int bb = mLo >> 10, nn = mLo & 1023;
                    size_t idx = ((size_t)(bb * kHeads + hh) * kSeq + nn) * kHd + dd;
                    *(__half2*)(dst + idx) = __floats2half2_rn(acc[mt][nt][0], acc[mt][nt][1]);
                }
                {
                    int bb = mHi >> 10, nn = mHi & 1023;
                    size_t idx = ((size_t)(bb * kHeads + hh) * kSeq + nn) * kHd + dd;
                    *(__half2*)(dst + idx) = __floats2half2_rn(acc[mt][nt][2], acc[mt][nt][3]);
                }
            } else {
                const float b0v = bias[f], b1v = bias[f + 1];
                *(float2*)(C + (size_t)mLo * kDim + f) =
                    make_float2(acc[mt][nt][0] + b0v, acc[mt][nt][1] + b1v);
                *(float2*)(C + (size_t)mHi * kDim + f) =
                    make_float2(acc[mt][nt][2] + b0v, acc[mt][nt][3] + b1v);
            }
        }
    }
}

// ---------------------------------------------------------------------------
// Flash attention: CTA = (b, h, 64 q-rows). 4 warps x 16 rows. d=64. fp16 in,
// fp32 accum/softmax. V stored transposed in smem so PV B-frags are half2.
// smem rows: 72 halves (144B == 16 mod 128 -> 4-bank row step, conflict-free).
// ---------------------------------------------------------------------------
__global__ __launch_bounds__(128)
void attn_kernel() {
    __shared__ __half sK [64][72];   // K tile / P tile / Q staging
    __shared__ __half sVt[64][72];   // V tile, transposed: [d][kv]

    const int bx = blockIdx.x;
    const int qt = bx & 15;
    const int bh = bx >> 4;
    const int bb = bh >> 4;
    const int hh = bh & 15;
    const int tid = threadIdx.x, warp = tid >> 5, lane = tid & 31;
    const int tg = lane >> 2, tl = lane & 3;

    const __half* Qp = g_q + (size_t)(bb * kHeads + hh) * kSeq * kHd;
    const __half* Kp = g_k + (size_t)(bb * kHeads + hh) * kSeq * kHd;
    const __half* Vp = g_v + (size_t)(bb * kHeads + hh) * kSeq * kHd;
    const int q0 = qt * 64;

    const int fr = tid >> 1;         // 0..63
    const int fc = (tid & 1) * 32;   // 0 / 32

    // Stage Q through smem, extract A-fragments for the 4 k-steps, pre-scaled.
#pragma unroll
    for (int j = 0; j < 4; j++)
        *(uint4*)&sK[fr][fc + 8 * j] = *(const uint4*)&Qp[(q0 + fr) * kHd + fc + 8 * j];
    __syncthreads();

    unsigned qf[4][4];
    {
        const __half2 sc2 = __floats2half2_rn(0.125f, 0.125f);  // exact scale
        const int r = warp * 16 + tg;
#pragma unroll
        for (int ks = 0; ks < 4; ks++) {
            __half2 a0 = __hmul2(*(const __half2*)&sK[r    ][ks * 16 + 2 * tl    ], sc2);
            __half2 a1 = __hmul2(*(const __half2*)&sK[r + 8][ks * 16 + 2 * tl    ], sc2);
            __half2 a2 = __hmul2(*(const __half2*)&sK[r    ][ks * 16 + 2 * tl + 8], sc2);
            __half2 a3 = __hmul2(*(const __half2*)&sK[r + 8][ks * 16 + 2 * tl + 8], sc2);
            qf[ks][0] = *(unsigned*)&a0;
            qf[ks][1] = *(unsigned*)&a1;
            qf[ks][2] = *(unsigned*)&a2;
            qf[ks][3] = *(unsigned*)&a3;
        }
    }
    __syncthreads();

    float o[8][4];
#pragma unroll
    for (int nt = 0; nt < 8; nt++)
#pragma unroll
        for (int i = 0; i < 4; i++) o[nt][i] = 0.f;
    float mrun0 = -1e30f, mrun1 = -1e30f, lrun0 = 0.f, lrun1 = 0.f;

    for (int t = 0; t < 16; t++) {
        // Fill K (row-major) and V (transposed) tiles
#pragma unroll
        for (int j = 0; j < 4; j++)
            *(uint4*)&sK[fr][fc + 8 * j] = *(const uint4*)&Kp[(t * 64 + fr) * kHd + fc + 8 * j];
#pragma unroll
        for (int j = 0; j < 4; j++) {
            uint4 v = *(const uint4*)&Vp[(t * 64 + fr) * kHd + fc + 8 * j];
            const __half* hv = (const __half*)&v;
#pragma unroll
            for (int e = 0; e < 8; e++) sVt[fc + 8 * j + e][fr] = hv[e];
        }
        __syncthreads();

        // S = (Q*scale) K^T
        float s[8][4];
#pragma unroll
        for (int nt = 0; nt < 8; nt++)
#pragma unroll
            for (int i = 0; i < 4; i++) s[nt][i] = 0.f;

#pragma unroll
        for (int ks = 0; ks < 4; ks++) {
            unsigned bfr[8][2];
#pragma unroll
            for (int nt = 0; nt < 8; nt++) {
                const int row = nt * 8 + tg;
                bfr[nt][0] = *(const unsigned*)&sK[row][ks * 16 + 2 * tl    ];
                bfr[nt][1] = *(const unsigned*)&sK[row][ks * 16 + 2 * tl + 8];
            }
#pragma unroll
            for (int nt = 0; nt < 8; nt++) mma_fp16(s[nt], qf[ks], bfr[nt]);
        }

        // Online softmax (rows tg / tg+8; quad shuffle covers columns)
        float mt0 = -1e30f, mt1 = -1e30f;
#pragma unroll
        for (int nt = 0; nt < 8; nt++) {
            mt0 = fmaxf(mt0, fmaxf(s[nt][0], s[nt][1]));
            mt1 = fmaxf(mt1, fmaxf(s[nt][2], s[nt][3]));
        }
        mt0 = qredmax(mt0);
        mt1 = qredmax(mt1);
        const float mn0 = fmaxf(mrun0, mt0), mn1 = fmaxf(mrun1, mt1);
        const float a0 = __expf(mrun0 - mn0), a1 = __expf(mrun1 - mn1);
        float sum0 = 0.f, sum1 = 0.f;
#pragma unroll
        for (int nt = 0; nt < 8; nt++) {
            s[nt][0] = __expf(s[nt][0] - mn0); sum0 += s[nt][0];
            s[nt][1] = __expf(s[nt][1] - mn0); sum0 += s[nt][1];
            s[nt][2] = __expf(s[nt][2] - mn1); sum1 += s[nt][2];
            s[nt][3] = __expf(s[nt][3] - mn1); sum1 += s[nt][3];
        }
        sum0 = qredsum(sum0);
        sum1 = qredsum(sum1);
        lrun0 = lrun0 * a0 + sum0;
        lrun1 = lrun1 * a1 + sum1;
        mrun0 = mn0;
        mrun1 = mn1;
#pragma unroll
        for (int nt = 0; nt < 8; nt++) {
            o[nt][0] *= a0; o[nt][1] *= a0; o[nt][2] *= a1; o[nt][3] *= a1;
        }

        __syncthreads();  // all warps done reading K from sK

        // P (fp16) through smem: warp-private 16 rows
        const int pr = warp * 16 + tg;
#pragma unroll
        for (int nt = 0; nt < 8; nt++) {
            *(__half2*)&sK[pr    ][nt * 8 + 2 * tl] = __floats2half2_rn(s[nt][0], s[nt][1]);
            *(__half2*)&sK[pr + 8][nt * 8 + 2 * tl] = __floats2half2_rn(s[nt][2], s[nt][3]);
        }
        __syncwarp();

        // O += P V
#pragma unroll
        for (int ks = 0; ks < 4; ks++) {
            unsigned pf[4];
            pf[0] = *(const unsigned*)&sK[pr    ][ks * 16 + 2 * tl    ];
            pf[1] = *(const unsigned*)&sK[pr + 8][ks * 16 + 2 * tl    ];
            pf[2] = *(const unsigned*)&sK[pr    ][ks * 16 + 2 * tl + 8];
            pf[3] = *(const unsigned*)&sK[pr + 8][ks * 16 + 2 * tl + 8];
            unsigned vf[8][2];
#pragma unroll
            for (int nt = 0; nt < 8; nt++) {
                const int rowd = nt * 8 + tg;
                vf[nt][0] = *(const unsigned*)&sVt[rowd][ks * 16 + 2 * tl    ];
                vf[nt][1] = *(const unsigned*)&sVt[rowd][ks * 16 + 2 * tl + 8];
            }
#pragma unroll
            for (int nt = 0; nt < 8; nt++) mma_fp16(o[nt], pf, vf[nt]);
        }
        __syncthreads();  // before next tile overwrites sK/sVt
    }

    // Epilogue: normalize, write att (half) as [b, n, h*64+d]
    const float inv0 = 1.f / lrun0, inv1 = 1.f / lrun1;
    const int r0 = q0 + warp * 16 + tg;
    const int r1 = r0 + 8;
#pragma unroll
    for (int nt = 0; nt < 8; nt++) {
        const int dd = nt * 8 + 2 * tl;
        *(__half2*)&g_att[(size_t)(bb * kSeq + r0) * kDim + hh * kHd + dd] =
            __floats2half2_rn(o[nt][0] * inv0, o[nt][1] * inv0);
        *(__half2*)&g_att[(size_t)(bb * kSeq + r1) * kDim + hh * kHd + dd] =
            __floats2half2_rn(o[nt][2] * inv1, o[nt][3] * inv1);
    }
}

// ---------------------------------------------------------------------------
extern "C" void kernel_launch(void* const* d_in, const int* in_sizes, int n_in,
                              void* d_out, int out_size) {
    (void)in_sizes; (void)n_in; (void)out_size;
    const float* x      = (const float*)d_in[0];
    const float* w_qkv  = (const float*)d_in[1];
    const float* w_proj = (const float*)d_in[2];
    const float* b_proj = (const float*)d_in[3];
    float* out = (float*)d_out;

    // 1) QKV projection (M=8192, N=3072, K=1024) -> scatter half to q/k/v
    gemm_fp16_kernel<0><<<dim3(3 * kDim / 128, kBatch * kSeq / 128), 256>>>(
        x, w_qkv, nullptr, nullptr);

    // 2) Flash attention per (b, h, 64-row q tile)
    attn_kernel<<<kBatch * kHeads * (kSeq / 64), 128>>>();

    // 3) Output projection + bias (M=8192, N=1024, K=1024)
    gemm_fp16_kernel<1><<<dim3(kDim / 128, kBatch * kSeq / 128), 256>>>(
        nullptr, w_proj, b_proj, out);
}

// round 11
// speedup vs baseline: 1.8238x; 1.2161x over previous
#include <cuda_runtime.h>
#include <cuda_fp16.h>
#include <cstdint>

// ---------------------------------------------------------------------------
// x[8,1024,1024] -> qkv proj -> 16-head attention -> out proj (+bias)
// Legacy mma.sync m16n8k16 fp16/fp32 (sm_100 base ISA: no tcgen05 available,
// per round-5 ptxas evidence). 64x64 warp tiles + ldmatrix + cp.async.
// ---------------------------------------------------------------------------

constexpr int kDim   = 1024;
constexpr int kBatch = 8;
constexpr int kSeq   = 1024;
constexpr int kHeads = 16;
constexpr int kHd    = 64;

// fp16 scratch (allocation-free rule: __device__ globals)
__device__ __half g_xh    [kBatch * kSeq * kDim];
__device__ __half g_wqkvh [3 * kDim * kDim];
__device__ __half g_wprojh[kDim * kDim];
__device__ __half g_q[kBatch * kHeads * kSeq * kHd];   // pre-scaled by 0.125
__device__ __half g_k[kBatch * kHeads * kSeq * kHd];
__device__ __half g_v[kBatch * kHeads * kSeq * kHd];
__device__ __half g_att[kBatch * kSeq * kDim];

// ------------------------------ helpers ------------------------------------
__device__ __forceinline__ uint32_t smem_u32(const void* p) {
    uint32_t a;
    asm("{ .reg .u64 t; cvta.to.shared.u64 t, %1; cvt.u32.u64 %0, t; }"
        : "=r"(a) : "l"(p));
    return a;
}
__device__ __forceinline__ void mma_fp16(float* c, const unsigned* a, const unsigned* b) {
    asm volatile(
        "mma.sync.aligned.m16n8k16.row.col.f32.f16.f16.f32 "
        "{%0,%1,%2,%3}, {%4,%5,%6,%7}, {%8,%9}, {%0,%1,%2,%3};"
        : "+f"(c[0]), "+f"(c[1]), "+f"(c[2]), "+f"(c[3])
        : "r"(a[0]), "r"(a[1]), "r"(a[2]), "r"(a[3]), "r"(b[0]), "r"(b[1]));
}
__device__ __forceinline__ void ldm_x4(unsigned& r0, unsigned& r1, unsigned& r2,
                                       unsigned& r3, uint32_t addr) {
    asm volatile("ldmatrix.sync.aligned.m8n8.x4.shared.b16 {%0,%1,%2,%3}, [%4];"
                 : "=r"(r0), "=r"(r1), "=r"(r2), "=r"(r3) : "r"(addr));
}
__device__ __forceinline__ void ldm_x4_t(unsigned& r0, unsigned& r1, unsigned& r2,
                                         unsigned& r3, uint32_t addr) {
    asm volatile("ldmatrix.sync.aligned.m8n8.x4.trans.shared.b16 {%0,%1,%2,%3}, [%4];"
                 : "=r"(r0), "=r"(r1), "=r"(r2), "=r"(r3) : "r"(addr));
}
__device__ __forceinline__ void cp16(uint32_t dst, const void* src) {
    asm volatile("cp.async.cg.shared.global [%0], [%1], 16;" :: "r"(dst), "l"(src));
}
__device__ __forceinline__ void cp_commit() {
    asm volatile("cp.async.commit_group;" ::: "memory");
}
template <int N>
__device__ __forceinline__ void cp_wait() {
    asm volatile("cp.async.wait_group %0;" :: "n"(N) : "memory");
}
__device__ __forceinline__ unsigned h2u(float a, float b) {
    __half2 h = __floats2half2_rn(a, b);
    return *reinterpret_cast<unsigned*>(&h);
}
__device__ __forceinline__ float qredmax(float v) {
    v = fmaxf(v, __shfl_xor_sync(0xffffffffu, v, 1));
    v = fmaxf(v, __shfl_xor_sync(0xffffffffu, v, 2));
    return v;
}
__device__ __forceinline__ float qredsum(float v) {
    v += __shfl_xor_sync(0xffffffffu, v, 1);
    v += __shfl_xor_sync(0xffffffffu, v, 2);
    return v;
}

// ---------------------------------------------------------------------------
// fp32 -> fp16 conversion (which: 0=x, 1=w_qkv, 2=w_proj)
// ---------------------------------------------------------------------------
__global__ void cvt_kernel(const float* __restrict__ src, int which, int n4) {
    int i = blockIdx.x * blockDim.x + threadIdx.x;
    if (i >= n4) return;
    __half* dst = (which == 0) ? g_xh : (which == 1) ? g_wqkvh : g_wprojh;
    float4 v = ((const float4*)src)[i];
    uint2 u;
    u.x = h2u(v.x, v.y);
    u.y = h2u(v.z, v.w);
    ((uint2*)dst)[i] = u;
}

// ---------------------------------------------------------------------------
// GEMM: C[m, f] = sum_c A[m, c] * B[f, c]   (fp16 K-major both; mma row.col)
// CTA 128x128, 4 warps (2Mx2N), warp tile 64x64. K-slab 64, cp.async double
// buffered. Rows padded to 72 halves (144B): ldmatrix 8-row phases hit 32
// distinct banks (144 % 128 = 16 -> 4-bank step per row).
// MODE 0: A=g_xh, B=g_wqkvh; scatter half to g_q (x0.125)/g_k/g_v
// MODE 1: A=g_att, B=g_wprojh; add bias, f32 out
// ---------------------------------------------------------------------------
constexpr uint32_t G_ROWB = 144;                   // bytes per smem row
constexpr uint32_t G_TILE = 128 * G_ROWB;          // 18432 B
constexpr uint32_t SMEM_G = 4 * G_TILE;            // A[2],B[2] = 73728 B
constexpr int kSlabs = kDim / 64;                  // 16

template <int MODE>
__global__ __launch_bounds__(128)
void gemm2(const float* __restrict__ bias, float* __restrict__ C) {
    extern __shared__ char sm[];
    const uint32_t sA = smem_u32(sm);
    const uint32_t sB = sA + 2 * G_TILE;
    const int tid = threadIdx.x, warp = tid >> 5, lane = tid & 31;
    const int wm = warp & 1, wn = warp >> 1;       // warp tile 64(M) x 64(N)
    const int tg = lane >> 2, tl = lane & 3;
    const int m0 = blockIdx.y * 128, n0 = blockIdx.x * 128;

    const __half* Ag = (MODE == 0) ? g_xh : g_att;
    const __half* Bg = (MODE == 0) ? g_wqkvh : g_wprojh;

    const __half* arow = Ag + (size_t)(m0 + tid) * kDim;
    const __half* brow = Bg + (size_t)(n0 + tid) * kDim;
    const uint32_t aRow = sA + tid * G_ROWB;
    const uint32_t bRow = sB + tid * G_ROWB;

    float acc[4][8][4];
#pragma unroll
    for (int mt = 0; mt < 4; mt++)
#pragma unroll
        for (int nt = 0; nt < 8; nt++)
#pragma unroll
            for (int i = 0; i < 4; i++) acc[mt][nt][i] = 0.f;

    // lane-dependent ldmatrix base offset (16 rows x 2 col-halves)
    const uint32_t lOff = (lane & 15) * G_ROWB + (lane >> 4) * 16;

    // prologue: slab 0
    {
#pragma unroll
        for (int c = 0; c < 8; c++) cp16(aRow + c * 16, arow + c * 8);
#pragma unroll
        for (int c = 0; c < 8; c++) cp16(bRow + c * 16, brow + c * 8);
        cp_commit();
    }

    for (int s = 0; s < kSlabs; s++) {
        if (s + 1 < kSlabs) {
            const int k0 = (s + 1) * 64;
            const uint32_t off = ((s + 1) & 1) * G_TILE;
#pragma unroll
            for (int c = 0; c < 8; c++) cp16(aRow + off + c * 16, arow + k0 + c * 8);
#pragma unroll
            for (int c = 0; c < 8; c++) cp16(bRow + off + c * 16, brow + k0 + c * 8);
            cp_commit();
            cp_wait<1>();
        } else {
            cp_wait<0>();
        }
        __syncthreads();

        const uint32_t aS = sA + (s & 1) * G_TILE + wm * 64 * G_ROWB + lOff;
        const uint32_t bS = sB + (s & 1) * G_TILE + wn * 64 * G_ROWB + lOff;
#pragma unroll
        for (int ks = 0; ks < 4; ks++) {
            unsigned af[4][4], bf[8][2];
#pragma unroll
            for (int mt = 0; mt < 4; mt++)
                ldm_x4(af[mt][0], af[mt][1], af[mt][2], af[mt][3],
                       aS + mt * 16 * G_ROWB + ks * 32);
#pragma unroll
            for (int np = 0; np < 4; np++) {
                unsigned r0, r1, r2, r3;
                ldm_x4(r0, r1, r2, r3, bS + np * 16 * G_ROWB + ks * 32);
                bf[2 * np][0] = r0; bf[2 * np + 1][0] = r1;
                bf[2 * np][1] = r2; bf[2 * np + 1][1] = r3;
            }
#pragma unroll
            for (int mt = 0; mt < 4; mt++)
#pragma unroll
                for (int nt = 0; nt < 8; nt++)
                    mma_fp16(acc[mt][nt], af[mt], bf[nt]);
        }
        __syncthreads();
    }

    // Epilogue
#pragma unroll
    for (int mt = 0; mt < 4; mt++) {
        const int mLo = m0 + wm * 64 + mt * 16 + tg;
        const int mHi = mLo + 8;
#pragma unroll
        for (int nt = 0; nt < 8; nt++) {
            const int f = n0 + wn * 64 + nt * 8 + 2 * tl;
            if (MODE == 0) {
                const int which = f >> 10;
                const int hh    = (f >> 6) & 15;
                const int dd    = f & 63;
                const float sc  = (which == 0) ? 0.125f : 1.f;   // fold q scale
                __half* dst = (which == 0) ? g_q : ((which == 1) ? g_k : g_v);
                {
                    int bb = mLo >> 10, nn = mLo & 1023;
                    size_t idx = ((size_t)(bb * kHeads + hh) * kSeq + nn) * kHd + dd;
                    *(__half2*)(dst + idx) =
                        __floats2half2_rn(acc[mt][nt][0] * sc, acc[mt][nt][1] * sc);
                }
                {
                    int bb = mHi >> 10, nn = mHi & 1023;
                    size_t idx = ((size_t)(bb * kHeads + hh) * kSeq + nn) * kHd + dd;
                    *(__half2*)(dst + idx) =
                        __floats2half2_rn(acc[mt][nt][2] * sc, acc[mt][nt][3] * sc);
                }
            } else {
                const float b0v = bias[f], b1v = bias[f + 1];
                *(float2*)(C + (size_t)mLo * kDim + f) =
                    make_float2(acc[mt][nt][0] + b0v, acc[mt][nt][1] + b1v);
                *(float2*)(C + (size_t)mHi * kDim + f) =
                    make_float2(acc[mt][nt][2] + b0v, acc[mt][nt][3] + b1v);
            }
        }
    }
}

// ---------------------------------------------------------------------------
// Flash attention: CTA = 128 q-rows of one (b,h); 4 warps x 32 rows.
// KV tiles 64, cp.async double-buffered. K frags via ldmatrix; V frags via
// ldmatrix.trans on natural [kv][d] layout; P kept in registers (C-frag of S
// repacks directly into A-frag of PV). Q pre-scaled in g_q.
// smem: Q[128 rows] + 2 x (K[64] + V[64]) rows of 144B = 55296 B.
// ---------------------------------------------------------------------------
constexpr uint32_t A_KV   = 128 * G_ROWB;            // Q region size: 18432
constexpr uint32_t A_TILE = 64 * G_ROWB;             // 9216
constexpr uint32_t SMEM_A = A_KV + 2 * 2 * A_TILE;   // 55296

__global__ __launch_bounds__(128)
void attn2() {
    extern __shared__ char sm[];
    const uint32_t sQ = smem_u32(sm);
    const int bx = blockIdx.x;
    const int qt = bx & 7;
    const int bh = bx >> 3;
    const int bb = bh >> 4;
    const int hh = bh & 15;
    const int tid = threadIdx.x, warp = tid >> 5, lane = tid & 31;
    const int tg = lane >> 2, tl = lane & 3;
    const int q0 = qt * 128;
    const int wq = warp * 32;

    const __half* Qp = g_q + (size_t)(bb * kHeads + hh) * kSeq * kHd;
    const __half* Kp = g_k + (size_t)(bb * kHeads + hh) * kSeq * kHd;
    const __half* Vp = g_v + (size_t)(bb * kHeads + hh) * kSeq * kHd;

    // KV loader: thread t -> row t>>1 (0..63), half (t&1) of the 128B row
    const int kvRow = tid >> 1, kvHalf = tid & 1;

    // prologue: KV tile 0
    {
        const __half* ks = Kp + (size_t)kvRow * kHd + kvHalf * 32;
        const __half* vs = Vp + (size_t)kvRow * kHd + kvHalf * 32;
        const uint32_t dK = sQ + A_KV + kvRow * G_ROWB + kvHalf * 64;
        const uint32_t dV = dK + A_TILE;
#pragma unroll
        for (int j = 0; j < 4; j++) cp16(dK + j * 16, ks + j * 8);
#pragma unroll
        for (int j = 0; j < 4; j++) cp16(dV + j * 16, vs + j * 8);
        cp_commit();
    }

    // Stage Q (pre-scaled by 0.125 at QKV epilogue)
    {
        const __half* qr = Qp + (size_t)(q0 + tid) * kHd;
        char* qd = sm + tid * G_ROWB;
#pragma unroll
        for (int j = 0; j < 8; j++)
            *(uint4*)(qd + j * 16) = *(const uint4*)(qr + j * 8);
    }
    __syncthreads();

    const uint32_t lOff = (lane & 15) * G_ROWB + (lane >> 4) * 16;
    unsigned qf[4][2][4];
    {
        const uint32_t qBase = sQ + wq * G_ROWB + lOff;
#pragma unroll
        for (int ks = 0; ks < 4; ks++)
#pragma unroll
            for (int mt = 0; mt < 2; mt++)
                ldm_x4(qf[ks][mt][0], qf[ks][mt][1], qf[ks][mt][2], qf[ks][mt][3],
                       qBase + mt * 16 * G_ROWB + ks * 32);
    }

    float o[2][8][4];
#pragma unroll
    for (int mt = 0; mt < 2; mt++)
#pragma unroll
        for (int nt = 0; nt < 8; nt++)
#pragma unroll
            for (int i = 0; i < 4; i++) o[mt][nt][i] = 0.f;
    float mrun[2][2] = {{-1e30f, -1e30f}, {-1e30f, -1e30f}};
    float lrun[2][2] = {{0.f, 0.f}, {0.f, 0.f}};

    for (int t = 0; t < 16; t++) {
        if (t + 1 < 16) {
            const uint32_t base = sQ + A_KV + ((t + 1) & 1) * 2 * A_TILE;
            const __half* ks = Kp + (size_t)((t + 1) * 64 + kvRow) * kHd + kvHalf * 32;
            const __half* vs = Vp + (size_t)((t + 1) * 64 + kvRow) * kHd + kvHalf * 32;
            const uint32_t dK = base + kvRow * G_ROWB + kvHalf * 64;
            const uint32_t dV = dK + A_TILE;
#pragma unroll
            for (int j = 0; j < 4; j++) cp16(dK + j * 16, ks + j * 8);
#pragma unroll
            for (int j = 0; j < 4; j++) cp16(dV + j * 16, vs + j * 8);
            cp_commit();
            cp_wait<1>();
        } else {
            cp_wait<0>();
        }
        __syncthreads();

        const uint32_t kB = sQ + A_KV + (t & 1) * 2 * A_TILE;
        const uint32_t vB = kB + A_TILE;

        // S = Q K^T  (Q pre-scaled)
        float s[2][8][4];
#pragma unroll
        for (int mt = 0; mt < 2; mt++)
#pragma unroll
            for (int nt = 0; nt < 8; nt++)
#pragma unroll
                for (int i = 0; i < 4; i++) s[mt][nt][i] = 0.f;

#pragma unroll
        for (int ks = 0; ks < 4; ks++) {
            unsigned bf[8][2];
#pragma unroll
            for (int np = 0; np < 4; np++) {
                unsigned r0, r1, r2, r3;
                ldm_x4(r0, r1, r2, r3, kB + np * 16 * G_ROWB + ks * 32 + lOff);
                bf[2 * np][0] = r0; bf[2 * np + 1][0] = r1;
                bf[2 * np][1] = r2; bf[2 * np + 1][1] = r3;
            }
#pragma unroll
            for (int mt = 0; mt < 2; mt++)
#pragma unroll
                for (int nt = 0; nt < 8; nt++)
                    mma_fp16(s[mt][nt], qf[ks][mt], bf[nt]);
        }

        // Online softmax: per mt, rows (tg) -> idx 0/1 and (tg+8) -> idx 2/3
#pragma unroll
        for (int mt = 0; mt < 2; mt++) {
            float t0 = -1e30f, t1 = -1e30f;
#pragma unroll
            for (int nt = 0; nt < 8; nt++) {
                t0 = fmaxf(t0, fmaxf(s[mt][nt][0], s[mt][nt][1]));
                t1 = fmaxf(t1, fmaxf(s[mt][nt][2], s[mt][nt][3]));
            }
            t0 = qredmax(t0);
            t1 = qredmax(t1);
            const float mn0 = fmaxf(mrun[mt][0], t0);
            const float mn1 = fmaxf(mrun[mt][1], t1);
            const float a0 = __expf(mrun[mt][0] - mn0);
            const float a1 = __expf(mrun[mt][1] - mn1);
            float s0 = 0.f, s1 = 0.f;
#pragma unroll
            for (int nt = 0; nt < 8; nt++) {
                s[mt][nt][0] = __expf(s[mt][nt][0] - mn0); s0 += s[mt][nt][0];
                s[mt][nt][1] = __expf(s[mt][nt][1] - mn0); s0 += s[mt][nt][1];
                s[mt][nt][2] = __expf(s[mt][nt][2] - mn1); s1 += s[mt][nt][2];
                s[mt][nt][3] = __expf(s[mt][nt][3] - mn1); s1 += s[mt][nt][3];
            }
            lrun[mt][0] = lrun[mt][0] * a0 + qredsum(s0);
            lrun[mt][1] = lrun[mt][1] * a1 + qredsum(s1);
            mrun[mt][0] = mn0;
            mrun[mt][1] = mn1;
#pragma unroll
            for (int nt = 0; nt < 8; nt++) {
                o[mt][nt][0] *= a0; o[mt][nt][1] *= a0;
                o[mt][nt][2] *= a1; o[mt][nt][3] *= a1;
            }
        }

        // O += P V : P repacked from S C-frags (rows tg/tg+8, cols 2tl..);
        // PV k-slice ks covers kv 16*ks..16*ks+15 = S nt pairs (2ks, 2ks+1).
        // V frags via ldmatrix.trans: B-frag (row=kv, col=d) from natural V.
#pragma unroll
        for (int ks = 0; ks < 4; ks++) {
            unsigned pf[2][4];
#pragma unroll
            for (int mt = 0; mt < 2; mt++) {
                pf[mt][0] = h2u(s[mt][2 * ks    ][0], s[mt][2 * ks    ][1]);
                pf[mt][1] = h2u(s[mt][2 * ks    ][2], s[mt][2 * ks    ][3]);
                pf[mt][2] = h2u(s[mt][2 * ks + 1][0], s[mt][2 * ks + 1][1]);
                pf[mt][3] = h2u(s[mt][2 * ks + 1][2], s[mt][2 * ks + 1][3]);
            }
            unsigned vf[8][2];
#pragma unroll
            for (int np = 0; np < 4; np++) {
                unsigned r0, r1, r2, r3;
                ldm_x4_t(r0, r1, r2, r3,
                         vB + ks * 16 * G_ROWB + np * 32 + lOff);
                vf[2 * np][0] = r0; vf[2 * np][1] = r1;
                vf[2 * np + 1][0] = r2; vf[2 * np + 1][1] = r3;
            }
#pragma unroll
            for (int mt = 0; mt < 2; mt++)
#pragma unroll
                for (int nt = 0; nt < 8; nt++)
                    mma_fp16(o[mt][nt], pf[mt], vf[nt]);
        }
        __syncthreads();
    }

    // Epilogue: normalize, write att (half) as [b, n, h*64+d]
#pragma unroll
    for (int mt = 0; mt < 2; mt++) {
        const float inv0 = 1.f / lrun[mt][0], inv1 = 1.f / lrun[mt][1];
        const int r0 = q0 + wq + mt * 16 + tg;
        const int r1 = r0 + 8;
#pragma unroll
        for (int nt = 0; nt < 8; nt++) {
            const int dd = nt * 8 + 2 * tl;
            *(__half2*)&g_att[(size_t)(bb * kSeq + r0) * kDim + hh * kHd + dd] =
                __floats2half2_rn(o[mt][nt][0] * inv0, o[mt][nt][1] * inv0);
            *(__half2*)&g_att[(size_t)(bb * kSeq + r1) * kDim + hh * kHd + dd] =
                __floats2half2_rn(o[mt][nt][2] * inv1, o[mt][nt][3] * inv1);
        }
    }
}

// ---------------------------------------------------------------------------
extern "C" void kernel_launch(void* const* d_in, const int* in_sizes, int n_in,
                              void* d_out, int out_size) {
    (void)in_sizes; (void)n_in; (void)out_size;
    const float* x      = (const float*)d_in[0];
    const float* w_qkv  = (const float*)d_in[1];
    const float* w_proj = (const float*)d_in[2];
    const float* b_proj = (const float*)d_in[3];
    float* out = (float*)d_out;

    cudaFuncSetAttribute(gemm2<0>, cudaFuncAttributeMaxDynamicSharedMemorySize, SMEM_G);
    cudaFuncSetAttribute(gemm2<1>, cudaFuncAttributeMaxDynamicSharedMemorySize, SMEM_G);
    cudaFuncSetAttribute(attn2, cudaFuncAttributeMaxDynamicSharedMemorySize, SMEM_A);

    // 0) fp32 -> fp16
    cvt_kernel<<<(kBatch * kSeq * kDim / 4 + 255) / 256, 256>>>(x, 0,
        kBatch * kSeq * kDim / 4);
    cvt_kernel<<<(3 * kDim * kDim / 4 + 255) / 256, 256>>>(w_qkv, 1,
        3 * kDim * kDim / 4);
    cvt_kernel<<<(kDim * kDim / 4 + 255) / 256, 256>>>(w_proj, 2,
        kDim * kDim / 4);

    // 1) QKV projection: M=8192, N=3072 -> g_q (x0.125) / g_k / g_v
    gemm2<0><<<dim3(3 * kDim / 128, kBatch * kSeq / 128), 128, SMEM_G>>>(
        nullptr, nullptr);

    // 2) Flash attention: 8 q-tiles x 128 heads
    attn2<<<kBatch * kHeads * (kSeq / 128), 128, SMEM_A>>>();

    // 3) Output projection + bias: M=8192, N=1024 -> f32 out
    gemm2<1><<<dim3(kDim / 128, kBatch * kSeq / 128), 128, SMEM_G>>>(
        b_proj, out);
}

// round 13
// speedup vs baseline: 1.8490x; 1.0138x over previous
#include <cuda_runtime.h>
#include <cuda_fp16.h>
#include <cstdint>

// ---------------------------------------------------------------------------
// x[8,1024,1024] -> qkv proj -> 16-head attention -> out proj (+bias)
// Legacy mma.sync m16n8k16 fp16/fp32 (sm_100 base ISA; tcgen05 unavailable).
// GEMMs: CTA 128x256, 8 warps (64x64 warp tiles), 3-stage cp.async pipeline.
// ---------------------------------------------------------------------------

constexpr int kDim   = 1024;
constexpr int kBatch = 8;
constexpr int kSeq   = 1024;
constexpr int kHeads = 16;
constexpr int kHd    = 64;

// fp16 scratch (allocation-free rule: __device__ globals)
__device__ __half g_xh    [kBatch * kSeq * kDim];
__device__ __half g_wqkvh [3 * kDim * kDim];
__device__ __half g_wprojh[kDim * kDim];
__device__ __half g_q[kBatch * kHeads * kSeq * kHd];   // pre-scaled by 0.125
__device__ __half g_k[kBatch * kHeads * kSeq * kHd];
__device__ __half g_v[kBatch * kHeads * kSeq * kHd];
__device__ __half g_att[kBatch * kSeq * kDim];

// ------------------------------ helpers ------------------------------------
__device__ __forceinline__ uint32_t smem_u32(const void* p) {
    uint32_t a;
    asm("{ .reg .u64 t; cvta.to.shared.u64 t, %1; cvt.u32.u64 %0, t; }"
        : "=r"(a) : "l"(p));
    return a;
}
__device__ __forceinline__ void mma_fp16(float* c, const unsigned* a, const unsigned* b) {
    asm volatile(
        "mma.sync.aligned.m16n8k16.row.col.f32.f16.f16.f32 "
        "{%0,%1,%2,%3}, {%4,%5,%6,%7}, {%8,%9}, {%0,%1,%2,%3};"
        : "+f"(c[0]), "+f"(c[1]), "+f"(c[2]), "+f"(c[3])
        : "r"(a[0]), "r"(a[1]), "r"(a[2]), "r"(a[3]), "r"(b[0]), "r"(b[1]));
}
__device__ __forceinline__ void ldm_x4(unsigned& r0, unsigned& r1, unsigned& r2,
                                       unsigned& r3, uint32_t addr) {
    asm volatile("ldmatrix.sync.aligned.m8n8.x4.shared.b16 {%0,%1,%2,%3}, [%4];"
                 : "=r"(r0), "=r"(r1), "=r"(r2), "=r"(r3) : "r"(addr));
}
__device__ __forceinline__ void ldm_x4_t(unsigned& r0, unsigned& r1, unsigned& r2,
                                         unsigned& r3, uint32_t addr) {
    asm volatile("ldmatrix.sync.aligned.m8n8.x4.trans.shared.b16 {%0,%1,%2,%3}, [%4];"
                 : "=r"(r0), "=r"(r1), "=r"(r2), "=r"(r3) : "r"(addr));
}
__device__ __forceinline__ void cp16(uint32_t dst, const void* src) {
    asm volatile("cp.async.cg.shared.global [%0], [%1], 16;" :: "r"(dst), "l"(src));
}
__device__ __forceinline__ void cp_commit() {
    asm volatile("cp.async.commit_group;" ::: "memory");
}
template <int N>
__device__ __forceinline__ void cp_wait() {
    asm volatile("cp.async.wait_group %0;" :: "n"(N) : "memory");
}
__device__ __forceinline__ unsigned h2u(float a, float b) {
    __half2 h = __floats2half2_rn(a, b);
    return *reinterpret_cast<unsigned*>(&h);
}
__device__ __forceinline__ float qredmax(float v) {
    v = fmaxf(v, __shfl_xor_sync(0xffffffffu, v, 1));
    v = fmaxf(v, __shfl_xor_sync(0xffffffffu, v, 2));
    return v;
}
__device__ __forceinline__ float qredsum(float v) {
    v += __shfl_xor_sync(0xffffffffu, v, 1);
    v += __shfl_xor_sync(0xffffffffu, v, 2);
    return v;
}

// ---------------------------------------------------------------------------
// fp32 -> fp16 conversion (which: 0=x, 1=w_qkv, 2=w_proj)
// ---------------------------------------------------------------------------
__global__ void cvt_kernel(const float* __restrict__ src, int which, int n4) {
    int i = blockIdx.x * blockDim.x + threadIdx.x;
    if (i >= n4) return;
    __half* dst = (which == 0) ? g_xh : (which == 1) ? g_wqkvh : g_wprojh;
    float4 v = ((const float4*)src)[i];
    uint2 u;
    u.x = h2u(v.x, v.y);
    u.y = h2u(v.z, v.w);
    ((uint2*)dst)[i] = u;
}

// ---------------------------------------------------------------------------
// GEMM: C[m, f] = sum_c A[m, c] * B[f, c]   (fp16 K-major both; mma row.col)
// CTA 128(M) x 256(N), 256 threads, 8 warps (wm=warp&1, wn=warp>>1).
// K-slab 64, 3-stage cp.async pipeline (prefetch distance 2).
// Rows padded to 144B: ldmatrix 8-row phases hit 32 distinct banks.
// MODE 0: A=g_xh, B=g_wqkvh; scatter half to g_q (x0.125)/g_k/g_v
// MODE 1: A=g_att, B=g_wprojh; add bias, f32 out
// ---------------------------------------------------------------------------
constexpr uint32_t G_ROWB = 144;
constexpr uint32_t A_ST   = 128 * G_ROWB;            // 18432
constexpr uint32_t B_ST   = 256 * G_ROWB;            // 36864
constexpr uint32_t G_ST   = A_ST + B_ST;             // 55296 per stage
constexpr uint32_t SMEM_G = 3 * G_ST;                // 165888
constexpr int kSlabs = kDim / 64;                    // 16

template <int MODE>
__global__ __launch_bounds__(256)
void gemm3(const float* __restrict__ bias, float* __restrict__ C) {
    extern __shared__ char sm[];
    const uint32_t sb = smem_u32(sm);
    const int tid = threadIdx.x, warp = tid >> 5, lane = tid & 31;
    const int wm = warp & 1, wn = warp >> 1;         // 2(M) x 4(N) warps
    const int tg = lane >> 2, tl = lane & 3;
    const int m0 = blockIdx.y * 128, n0 = blockIdx.x * 256;

    const __half* Ag = (MODE == 0) ? g_xh : g_att;
    const __half* Bg = (MODE == 0) ? g_wqkvh : g_wprojh;

    // Loader mapping: A row=tid>>1 half=(tid&1) (4 cp16); B row=tid (8 cp16)
    const int aR = tid >> 1, aH = tid & 1;
    const __half* aG = Ag + (size_t)(m0 + aR) * kDim + aH * 32;
    const __half* bG = Bg + (size_t)(n0 + tid) * kDim;
    const uint32_t aD = sb + aR * G_ROWB + aH * 64;
    const uint32_t bD = sb + A_ST + tid * G_ROWB;

    float acc[4][8][4];
#pragma unroll
    for (int mt = 0; mt < 4; mt++)
#pragma unroll
        for (int nt = 0; nt < 8; nt++)
#pragma unroll
            for (int i = 0; i < 4; i++) acc[mt][nt][i] = 0.f;

    const uint32_t lOff = (lane & 15) * G_ROWB + (lane >> 4) * 16;

    // prologue: slabs 0 and 1
#pragma unroll
    for (int p = 0; p < 2; p++) {
        const uint32_t off = p * G_ST;
        const int k0 = p * 64;
#pragma unroll
        for (int c = 0; c < 4; c++) cp16(aD + off + c * 16, aG + k0 + c * 8);
#pragma unroll
        for (int c = 0; c < 8; c++) cp16(bD + off + c * 16, bG + k0 + c * 8);
        cp_commit();
    }

    for (int s = 0; s < kSlabs; s++) {
        if (s + 2 < kSlabs) {
            const uint32_t off = ((s + 2) % 3) * G_ST;
            const int k0 = (s + 2) * 64;
#pragma unroll
            for (int c = 0; c < 4; c++) cp16(aD + off + c * 16, aG + k0 + c * 8);
#pragma unroll
            for (int c = 0; c < 8; c++) cp16(bD + off + c * 16, bG + k0 + c * 8);
            cp_commit();
            cp_wait<2>();
        } else if (s + 1 < kSlabs) {
            cp_wait<1>();
        } else {
            cp_wait<0>();
        }
        __syncthreads();   // stage s ready, prior consumers done

        const uint32_t st = sb + (s % 3) * G_ST;
        const uint32_t aS = st + wm * 64 * G_ROWB + lOff;
        const uint32_t bS = st + A_ST + wn * 64 * G_ROWB + lOff;
#pragma unroll
        for (int ks = 0; ks < 4; ks++) {
            unsigned af[4][4], bf[8][2];
#pragma unroll
            for (int mt = 0; mt < 4; mt++)
                ldm_x4(af[mt][0], af[mt][1], af[mt][2], af[mt][3],
                       aS + mt * 16 * G_ROWB + ks * 32);
#pragma unroll
            for (int np = 0; np < 4; np++) {
                unsigned r0, r1, r2, r3;
                ldm_x4(r0, r1, r2, r3, bS + np * 16 * G_ROWB + ks * 32);
                bf[2 * np][0] = r0; bf[2 * np + 1][0] = r1;
                bf[2 * np][1] = r2; bf[2 * np + 1][1] = r3;
            }
#pragma unroll
            for (int mt = 0; mt < 4; mt++)
#pragma unroll
                for (int nt = 0; nt < 8; nt++)
                    mma_fp16(acc[mt][nt], af[mt], bf[nt]);
        }
        __syncthreads();   // all warps done with stage s before it is refilled
    }

    // Epilogue
#pragma unroll
    for (int mt = 0; mt < 4; mt++) {
        const int mLo = m0 + wm * 64 + mt * 16 + tg;
        const int mHi = mLo + 8;
#pragma unroll
        for (int nt = 0; nt < 8; nt++) {
            const int f = n0 + wn * 64 + nt * 8 + 2 * tl;
            if (MODE == 0) {
                const int which = f >> 10;
                const int hh    = (f >> 6) & 15;
                const int dd    = f & 63;
                const float sc  = (which == 0) ? 0.125f : 1.f;   // fold q scale
                __half* dst = (which == 0) ? g_q : ((which == 1) ? g_k : g_v);
                {
                    int bb = mLo >> 10, nn = mLo & 1023;
                    size_t idx = ((size_t)(bb * kHeads + hh) * kSeq + nn) * kHd + dd;
                    *(__half2*)(dst + idx) =
                        __floats2half2_rn(acc[mt][nt][0] * sc, acc[mt][nt][1] * sc);
                }
                {
                    int bb = mHi >> 10, nn = mHi & 1023;
                    size_t idx = ((size_t)(bb * kHeads + hh) * kSeq + nn) * kHd + dd;
                    *(__half2*)(dst + idx) =
                        __floats2half2_rn(acc[mt][nt][2] * sc, acc[mt][nt][3] * sc);
                }
            } else {
                const float b0v = bias[f], b1v = bias[f + 1];
                *(float2*)(C + (size_t)mLo * kDim + f) =
                    make_float2(acc[mt][nt][0] + b0v, acc[mt][nt][1] + b1v);
                *(float2*)(C + (size_t)mHi * kDim + f) =
                    make_float2(acc[mt][nt][2] + b0v, acc[mt][nt][3] + b1v);
            }
        }
    }
}

// ---------------------------------------------------------------------------
// Flash attention: CTA = 128 q-rows of one (b,h); 4 warps x 32 rows.
// KV tiles 64, cp.async double-buffered. K frags via ldmatrix; V frags via
// ldmatrix.trans on natural [kv][d] layout; P kept in registers. Q pre-scaled.
// ---------------------------------------------------------------------------
constexpr uint32_t A_KV   = 128 * G_ROWB;            // Q region size: 18432
constexpr uint32_t A_TILE = 64 * G_ROWB;             // 9216
constexpr uint32_t SMEM_A = A_KV + 2 * 2 * A_TILE;   // 55296

__global__ __launch_bounds__(128)
void attn2() {
    extern __shared__ char sm[];
    const uint32_t sQ = smem_u32(sm);
    const int bx = blockIdx.x;
    const int qt = bx & 7;
    const int bh = bx >> 3;
    const int bb = bh >> 4;
    const int hh = bh & 15;
    const int tid = threadIdx.x, warp = tid >> 5, lane = tid & 31;
    const int tg = lane >> 2, tl = lane & 3;
    const int q0 = qt * 128;
    const int wq = warp * 32;

    const __half* Qp = g_q + (size_t)(bb * kHeads + hh) * kSeq * kHd;
    const __half* Kp = g_k + (size_t)(bb * kHeads + hh) * kSeq * kHd;
    const __half* Vp = g_v + (size_t)(bb * kHeads + hh) * kSeq * kHd;

    const int kvRow = tid >> 1, kvHalf = tid & 1;

    // prologue: KV tile 0
    {
        const __half* ks = Kp + (size_t)kvRow * kHd + kvHalf * 32;
        const __half* vs = Vp + (size_t)kvRow * kHd + kvHalf * 32;
        const uint32_t dK = sQ + A_KV + kvRow * G_ROWB + kvHalf * 64;
        const uint32_t dV = dK + A_TILE;
#pragma unroll
        for (int j = 0; j < 4; j++) cp16(dK + j * 16, ks + j * 8);
#pragma unroll
        for (int j = 0; j < 4; j++) cp16(dV + j * 16, vs + j * 8);
        cp_commit();
    }

    // Stage Q (pre-scaled by 0.125 at QKV epilogue)
    {
        const __half* qr = Qp + (size_t)(q0 + tid) * kHd;
        char* qd = sm + tid * G_ROWB;
#pragma unroll
        for (int j = 0; j < 8; j++)
            *(uint4*)(qd + j * 16) = *(const uint4*)(qr + j * 8);
    }
    __syncthreads();

    const uint32_t lOff = (lane & 15) * G_ROWB + (lane >> 4) * 16;
    unsigned qf[4][2][4];
    {
        const uint32_t qBase = sQ + wq * G_ROWB + lOff;
#pragma unroll
        for (int ks = 0; ks < 4; ks++)
#pragma unroll
            for (int mt = 0; mt < 2; mt++)
                ldm_x4(qf[ks][mt][0], qf[ks][mt][1], qf[ks][mt][2], qf[ks][mt][3],
                       qBase + mt * 16 * G_ROWB + ks * 32);
    }

    float o[2][8][4];
#pragma unroll
    for (int mt = 0; mt < 2; mt++)
#pragma unroll
        for (int nt = 0; nt < 8; nt++)
#pragma unroll
            for (int i = 0; i < 4; i++) o[mt][nt][i] = 0.f;
    float mrun[2][2] = {{-1e30f, -1e30f}, {-1e30f, -1e30f}};
    float lrun[2][2] = {{0.f, 0.f}, {0.f, 0.f}};

    for (int t = 0; t < 16; t++) {
        if (t + 1 < 16) {
            const uint32_t base = sQ + A_KV + ((t + 1) & 1) * 2 * A_TILE;
            const __half* ks = Kp + (size_t)((t + 1) * 64 + kvRow) * kHd + kvHalf * 32;
            const __half* vs = Vp + (size_t)((t + 1) * 64 + kvRow) * kHd + kvHalf * 32;
            const uint32_t dK = base + kvRow * G_ROWB + kvHalf * 64;
            const uint32_t dV = dK + A_TILE;
#pragma unroll
            for (int j = 0; j < 4; j++) cp16(dK + j * 16, ks + j * 8);
#pragma unroll
            for (int j = 0; j < 4; j++) cp16(dV + j * 16, vs + j * 8);
            cp_commit();
            cp_wait<1>();
        } else {
            cp_wait<0>();
        }
        __syncthreads();

        const uint32_t kB = sQ + A_KV + (t & 1) * 2 * A_TILE;
        const uint32_t vB = kB + A_TILE;

        // S = Q K^T
        float s[2][8][4];
#pragma unroll
        for (int mt = 0; mt < 2; mt++)
#pragma unroll
            for (int nt = 0; nt < 8; nt++)
#pragma unroll
                for (int i = 0; i < 4; i++) s[mt][nt][i] = 0.f;

#pragma unroll
        for (int ks = 0; ks < 4; ks++) {
            unsigned bf[8][2];
#pragma unroll
            for (int np = 0; np < 4; np++) {
                unsigned r0, r1, r2, r3;
                ldm_x4(r0, r1, r2, r3, kB + np * 16 * G_ROWB + ks * 32 + lOff);
                bf[2 * np][0] = r0; bf[2 * np + 1][0] = r1;
                bf[2 * np][1] = r2; bf[2 * np + 1][1] = r3;
            }
#pragma unroll
            for (int mt = 0; mt < 2; mt++)
#pragma unroll
                for (int nt = 0; nt < 8; nt++)
                    mma_fp16(s[mt][nt], qf[ks][mt], bf[nt]);
        }

        // Online softmax
#pragma unroll
        for (int mt = 0; mt < 2; mt++) {
            float t0 = -1e30f, t1 = -1e30f;
#pragma unroll
            for (int nt = 0; nt < 8; nt++) {
                t0 = fmaxf(t0, fmaxf(s[mt][nt][0], s[mt][nt][1]));
                t1 = fmaxf(t1, fmaxf(s[mt][nt][2], s[mt][nt][3]));
            }
            t0 = qredmax(t0);
            t1 = qredmax(t1);
            const float mn0 = fmaxf(mrun[mt][0], t0);
            const float mn1 = fmaxf(mrun[mt][1], t1);
            const float a0 = __expf(mrun[mt][0] - mn0);
            const float a1 = __expf(mrun[mt][1] - mn1);
            float s0 = 0.f, s1 = 0.f;
#pragma unroll
            for (int nt = 0; nt < 8; nt++) {
                s[mt][nt][0] = __expf(s[mt][nt][0] - mn0); s0 += s[mt][nt][0];
                s[mt][nt][1] = __expf(s[mt][nt][1] - mn0); s0 += s[mt][nt][1];
                s[mt][nt][2] = __expf(s[mt][nt][2] - mn1); s1 += s[mt][nt][2];
                s[mt][nt][3] = __expf(s[mt][nt][3] - mn1); s1 += s[mt][nt][3];
            }
            lrun[mt][0] = lrun[mt][0] * a0 + qredsum(s0);
            lrun[mt][1] = lrun[mt][1] * a1 + qredsum(s1);
            mrun[mt][0] = mn0;
            mrun[mt][1] = mn1;
#pragma unroll
            for (int nt = 0; nt < 8; nt++) {
                o[mt][nt][0] *= a0; o[mt][nt][1] *= a0;
                o[mt][nt][2] *= a1; o[mt][nt][3] *= a1;
            }
        }

        // O += P V (register-resident P; V frags via ldmatrix.trans)
#pragma unroll
        for (int ks = 0; ks < 4; ks++) {
            unsigned pf[2][4];
#pragma unroll
            for (int mt = 0; mt < 2; mt++) {
                pf[mt][0] = h2u(s[mt][2 * ks    ][0], s[mt][2 * ks    ][1]);
                pf[mt][1] = h2u(s[mt][2 * ks    ][2], s[mt][2 * ks    ][3]);
                pf[mt][2] = h2u(s[mt][2 * ks + 1][0], s[mt][2 * ks + 1][1]);
                pf[mt][3] = h2u(s[mt][2 * ks + 1][2], s[mt][2 * ks + 1][3]);
            }
            unsigned vf[8][2];
#pragma unroll
            for (int np = 0; np < 4; np++) {
                unsigned r0, r1, r2, r3;
                ldm_x4_t(r0, r1, r2, r3,
                         vB + ks * 16 * G_ROWB + np * 32 + lOff);
                vf[2 * np][0] = r0; vf[2 * np][1] = r1;
                vf[2 * np + 1][0] = r2; vf[2 * np + 1][1] = r3;
            }
#pragma unroll
            for (int mt = 0; mt < 2; mt++)
#pragma unroll
                for (int nt = 0; nt < 8; nt++)
                    mma_fp16(o[mt][nt], pf[mt], vf[nt]);
        }
        __syncthreads();
    }

    // Epilogue: normalize, write att (half) as [b, n, h*64+d]
#pragma unroll
    for (int mt = 0; mt < 2; mt++) {
        const float inv0 = 1.f / lrun[mt][0], inv1 = 1.f / lrun[mt][1];
        const int r0 = q0 + wq + mt * 16 + tg;
        const int r1 = r0 + 8;
#pragma unroll
        for (int nt = 0; nt < 8; nt++) {
            const int dd = nt * 8 + 2 * tl;
            *(__half2*)&g_att[(size_t)(bb * kSeq + r0) * kDim + hh * kHd + dd] =
                __floats2half2_rn(o[mt][nt][0] * inv0, o[mt][nt][1] * inv0);
            *(__half2*)&g_att[(size_t)(bb * kSeq + r1) * kDim + hh * kHd + dd] =
                __floats2half2_rn(o[mt][nt][2] * inv1, o[mt][nt][3] * inv1);
        }
    }
}

// ---------------------------------------------------------------------------
extern "C" void kernel_launch(void* const* d_in, const int* in_sizes, int n_in,
                              void* d_out, int out_size) {
    (void)in_sizes; (void)n_in; (void)out_size;
    const float* x      = (const float*)d_in[0];
    const float* w_qkv  = (const float*)d_in[1];
    const float* w_proj = (const float*)d_in[2];
    const float* b_proj = (const float*)d_in[3];
    float* out = (float*)d_out;

    cudaFuncSetAttribute(gemm3<0>, cudaFuncAttributeMaxDynamicSharedMemorySize, SMEM_G);
    cudaFuncSetAttribute(gemm3<1>, cudaFuncAttributeMaxDynamicSharedMemorySize, SMEM_G);
    cudaFuncSetAttribute(attn2, cudaFuncAttributeMaxDynamicSharedMemorySize, SMEM_A);

    // 0) fp32 -> fp16
    cvt_kernel<<<(kBatch * kSeq * kDim / 4 + 255) / 256, 256>>>(x, 0,
        kBatch * kSeq * kDim / 4);
    cvt_kernel<<<(3 * kDim * kDim / 4 + 255) / 256, 256>>>(w_qkv, 1,
        3 * kDim * kDim / 4);
    cvt_kernel<<<(kDim * kDim / 4 + 255) / 256, 256>>>(w_proj, 2,
        kDim * kDim / 4);

    // 1) QKV projection: M=8192, N=3072 -> g_q (x0.125) / g_k / g_v
    gemm3<0><<<dim3(3 * kDim / 256, kBatch * kSeq / 128), 256, SMEM_G>>>(
        nullptr, nullptr);

    // 2) Flash attention: 8 q-tiles x 128 heads
    attn2<<<kBatch * kHeads * (kSeq / 128), 128, SMEM_A>>>();

    // 3) Output projection + bias: M=8192, N=1024 -> f32 out
    gemm3<1><<<dim3(kDim / 256, kBatch * kSeq / 128), 256, SMEM_G>>>(
        b_proj, out);
}

// round 15
// speedup vs baseline: 2.1174x; 1.1452x over previous
#include <cuda_runtime.h>
#include <cuda_fp16.h>
#include <cstdint>

// ---------------------------------------------------------------------------
// x[8,1024,1024] -> qkv proj -> 16-head attention -> out proj (+bias)
// Legacy mma.sync m16n8k16 fp16/fp32. GEMMs: CTA 128x256, 512 threads,
// 16 warps (4Mx4N, warp tile 32x64), 3-stage cp.async pipeline.
// Round-13 evidence: latency-bound at 8 warps/SM -> double the warp pool.
// ---------------------------------------------------------------------------

constexpr int kDim   = 1024;
constexpr int kBatch = 8;
constexpr int kSeq   = 1024;
constexpr int kHeads = 16;
constexpr int kHd    = 64;

// fp16 scratch (allocation-free rule: __device__ globals)
__device__ __half g_xh    [kBatch * kSeq * kDim];
__device__ __half g_wqkvh [3 * kDim * kDim];
__device__ __half g_wprojh[kDim * kDim];
__device__ __half g_q[kBatch * kHeads * kSeq * kHd];   // pre-scaled by 0.125
__device__ __half g_k[kBatch * kHeads * kSeq * kHd];
__device__ __half g_v[kBatch * kHeads * kSeq * kHd];
__device__ __half g_att[kBatch * kSeq * kDim];

// ------------------------------ helpers ------------------------------------
__device__ __forceinline__ uint32_t smem_u32(const void* p) {
    uint32_t a;
    asm("{ .reg .u64 t; cvta.to.shared.u64 t, %1; cvt.u32.u64 %0, t; }"
        : "=r"(a) : "l"(p));
    return a;
}
__device__ __forceinline__ void mma_fp16(float* c, const unsigned* a, const unsigned* b) {
    asm volatile(
        "mma.sync.aligned.m16n8k16.row.col.f32.f16.f16.f32 "
        "{%0,%1,%2,%3}, {%4,%5,%6,%7}, {%8,%9}, {%0,%1,%2,%3};"
        : "+f"(c[0]), "+f"(c[1]), "+f"(c[2]), "+f"(c[3])
        : "r"(a[0]), "r"(a[1]), "r"(a[2]), "r"(a[3]), "r"(b[0]), "r"(b[1]));
}
__device__ __forceinline__ void ldm_x4(unsigned& r0, unsigned& r1, unsigned& r2,
                                       unsigned& r3, uint32_t addr) {
    asm volatile("ldmatrix.sync.aligned.m8n8.x4.shared.b16 {%0,%1,%2,%3}, [%4];"
                 : "=r"(r0), "=r"(r1), "=r"(r2), "=r"(r3) : "r"(addr));
}
__device__ __forceinline__ void ldm_x4_t(unsigned& r0, unsigned& r1, unsigned& r2,
                                         unsigned& r3, uint32_t addr) {
    asm volatile("ldmatrix.sync.aligned.m8n8.x4.trans.shared.b16 {%0,%1,%2,%3}, [%4];"
                 : "=r"(r0), "=r"(r1), "=r"(r2), "=r"(r3) : "r"(addr));
}
__device__ __forceinline__ void cp16(uint32_t dst, const void* src) {
    asm volatile("cp.async.cg.shared.global [%0], [%1], 16;" :: "r"(dst), "l"(src));
}
__device__ __forceinline__ void cp_commit() {
    asm volatile("cp.async.commit_group;" ::: "memory");
}
template <int N>
__device__ __forceinline__ void cp_wait() {
    asm volatile("cp.async.wait_group %0;" :: "n"(N) : "memory");
}
__device__ __forceinline__ unsigned h2u(float a, float b) {
    __half2 h = __floats2half2_rn(a, b);
    return *reinterpret_cast<unsigned*>(&h);
}
__device__ __forceinline__ float qredmax(float v) {
    v = fmaxf(v, __shfl_xor_sync(0xffffffffu, v, 1));
    v = fmaxf(v, __shfl_xor_sync(0xffffffffu, v, 2));
    return v;
}
__device__ __forceinline__ float qredsum(float v) {
    v += __shfl_xor_sync(0xffffffffu, v, 1);
    v += __shfl_xor_sync(0xffffffffu, v, 2);
    return v;
}

// ---------------------------------------------------------------------------
// fp32 -> fp16 conversion (which: 0=x, 1=w_qkv, 2=w_proj)
// ---------------------------------------------------------------------------
__global__ void cvt_kernel(const float* __restrict__ src, int which, int n4) {
    int i = blockIdx.x * blockDim.x + threadIdx.x;
    if (i >= n4) return;
    __half* dst = (which == 0) ? g_xh : (which == 1) ? g_wqkvh : g_wprojh;
    float4 v = ((const float4*)src)[i];
    uint2 u;
    u.x = h2u(v.x, v.y);
    u.y = h2u(v.z, v.w);
    ((uint2*)dst)[i] = u;
}

// ---------------------------------------------------------------------------
// GEMM: C[m, f] = sum_c A[m, c] * B[f, c]   (fp16 K-major both; mma row.col)
// CTA 128(M) x 256(N), 512 threads, 16 warps: wm=warp&3 (32-row group),
// wn=warp>>2 (64-col group). Warp tile 32x64. K-slab 64, 3-stage cp.async.
// Rows padded to 144B: ldmatrix 8-row phases hit 32 distinct banks.
// MODE 0: A=g_xh, B=g_wqkvh; scatter half to g_q (x0.125)/g_k/g_v
// MODE 1: A=g_att, B=g_wprojh; add bias, f32 out
// ---------------------------------------------------------------------------
constexpr uint32_t G_ROWB = 144;
constexpr uint32_t A_ST   = 128 * G_ROWB;            // 18432
constexpr uint32_t B_ST   = 256 * G_ROWB;            // 36864
constexpr uint32_t G_ST   = A_ST + B_ST;             // 55296 per stage
constexpr uint32_t SMEM_G = 3 * G_ST;                // 165888
constexpr int kSlabs = kDim / 64;                    // 16

template <int MODE>
__global__ __launch_bounds__(512, 1)
void gemm4(const float* __restrict__ bias, float* __restrict__ C) {
    extern __shared__ char sm[];
    const uint32_t sb = smem_u32(sm);
    const int tid = threadIdx.x, warp = tid >> 5, lane = tid & 31;
    const int wm = warp & 3, wn = warp >> 2;         // 4(M) x 4(N) warps
    const int tg = lane >> 2, tl = lane & 3;
    const int m0 = blockIdx.y * 128, n0 = blockIdx.x * 256;

    const __half* Ag = (MODE == 0) ? g_xh : g_att;
    const __half* Bg = (MODE == 0) ? g_wqkvh : g_wprojh;

    // Loaders: A 128 rows -> 4 thr/row, 2 cp16 each. B 256 rows -> 2 thr/row,
    // 4 cp16 each.
    const int aR = tid >> 2, aQ = tid & 3;           // quarter = 32B = 16 halves
    const int bR = tid >> 1, bH = tid & 1;           // half = 64B = 32 halves
    const __half* aG = Ag + (size_t)(m0 + aR) * kDim + aQ * 16;
    const __half* bG = Bg + (size_t)(n0 + bR) * kDim + bH * 32;
    const uint32_t aD = sb + aR * G_ROWB + aQ * 32;
    const uint32_t bD = sb + A_ST + bR * G_ROWB + bH * 64;

    float acc[2][8][4];
#pragma unroll
    for (int mt = 0; mt < 2; mt++)
#pragma unroll
        for (int nt = 0; nt < 8; nt++)
#pragma unroll
            for (int i = 0; i < 4; i++) acc[mt][nt][i] = 0.f;

    const uint32_t lOff = (lane & 15) * G_ROWB + (lane >> 4) * 16;

    // prologue: slabs 0 and 1
#pragma unroll
    for (int p = 0; p < 2; p++) {
        const uint32_t off = p * G_ST;
        const int k0 = p * 64;
        cp16(aD + off,      aG + k0);
        cp16(aD + off + 16, aG + k0 + 8);
#pragma unroll
        for (int c = 0; c < 4; c++) cp16(bD + off + c * 16, bG + k0 + c * 8);
        cp_commit();
    }

    for (int s = 0; s < kSlabs; s++) {
        if (s + 2 < kSlabs) {
            const uint32_t off = ((s + 2) % 3) * G_ST;
            const int k0 = (s + 2) * 64;
            cp16(aD + off,      aG + k0);
            cp16(aD + off + 16, aG + k0 + 8);
#pragma unroll
            for (int c = 0; c < 4; c++) cp16(bD + off + c * 16, bG + k0 + c * 8);
            cp_commit();
            cp_wait<2>();
        } else if (s + 1 < kSlabs) {
            cp_wait<1>();
        } else {
            cp_wait<0>();
        }
        __syncthreads();   // stage s ready, prior consumers done

        const uint32_t st = sb + (s % 3) * G_ST;
        const uint32_t aS = st + wm * 32 * G_ROWB + lOff;
        const uint32_t bS = st + A_ST + wn * 64 * G_ROWB + lOff;
#pragma unroll
        for (int ks = 0; ks < 4; ks++) {
            unsigned af[2][4], bf[8][2];
#pragma unroll
            for (int mt = 0; mt < 2; mt++)
                ldm_x4(af[mt][0], af[mt][1], af[mt][2], af[mt][3],
                       aS + mt * 16 * G_ROWB + ks * 32);
#pragma unroll
            for (int np = 0; np < 4; np++) {
                unsigned r0, r1, r2, r3;
                ldm_x4(r0, r1, r2, r3, bS + np * 16 * G_ROWB + ks * 32);
                bf[2 * np][0] = r0; bf[2 * np + 1][0] = r1;
                bf[2 * np][1] = r2; bf[2 * np + 1][1] = r3;
            }
#pragma unroll
            for (int mt = 0; mt < 2; mt++)
#pragma unroll
                for (int nt = 0; nt < 8; nt++)
                    mma_fp16(acc[mt][nt], af[mt], bf[nt]);
        }
        __syncthreads();   // all warps done with stage s before it is refilled
    }

    // Epilogue
#pragma unroll
    for (int mt = 0; mt < 2; mt++) {
        const int mLo = m0 + wm * 32 + mt * 16 + tg;
        const int mHi = mLo + 8;
#pragma unroll
        for (int nt = 0; nt < 8; nt++) {
            const int f = n0 + wn * 64 + nt * 8 + 2 * tl;
            if (MODE == 0) {
                const int which = f >> 10;
                const int hh    = (f >> 6) & 15;
                const int dd    = f & 63;
                const float sc  = (which == 0) ? 0.125f : 1.f;   // fold q scale
                __half* dst = (which == 0) ? g_q : ((which == 1) ? g_k : g_v);
                {
                    int bb = mLo >> 10, nn = mLo & 1023;
                    size_t idx = ((size_t)(bb * kHeads + hh) * kSeq + nn) * kHd + dd;
                    *(__half2*)(dst + idx) =
                        __floats2half2_rn(acc[mt][nt][0] * sc, acc[mt][nt][1] * sc);
                }
                {
                    int bb = mHi >> 10, nn = mHi & 1023;
                    size_t idx = ((size_t)(bb * kHeads + hh) * kSeq + nn) * kHd + dd;
                    *(__half2*)(dst + idx) =
                        __floats2half2_rn(acc[mt][nt][2] * sc, acc[mt][nt][3] * sc);
                }
            } else {
                const float b0v = bias[f], b1v = bias[f + 1];
                *(float2*)(C + (size_t)mLo * kDim + f) =
                    make_float2(acc[mt][nt][0] + b0v, acc[mt][nt][1] + b1v);
                *(float2*)(C + (size_t)mHi * kDim + f) =
                    make_float2(acc[mt][nt][2] + b0v, acc[mt][nt][3] + b1v);
            }
        }
    }
}

// ---------------------------------------------------------------------------
// Flash attention: CTA = 128 q-rows of one (b,h); 4 warps x 32 rows.
// KV tiles 64, cp.async double-buffered. K frags via ldmatrix; V frags via
// ldmatrix.trans on natural [kv][d] layout; P kept in registers. Q pre-scaled.
// ---------------------------------------------------------------------------
constexpr uint32_t A_KV   = 128 * G_ROWB;            // Q region size: 18432
constexpr uint32_t A_TILE = 64 * G_ROWB;             // 9216
constexpr uint32_t SMEM_A = A_KV + 2 * 2 * A_TILE;   // 55296

__global__ __launch_bounds__(128)
void attn2() {
    extern __shared__ char sm[];
    const uint32_t sQ = smem_u32(sm);
    const int bx = blockIdx.x;
    const int qt = bx & 7;
    const int bh = bx >> 3;
    const int bb = bh >> 4;
    const int hh = bh & 15;
    const int tid = threadIdx.x, warp = tid >> 5, lane = tid & 31;
    const int tg = lane >> 2, tl = lane & 3;
    const int q0 = qt * 128;
    const int wq = warp * 32;

    const __half* Qp = g_q + (size_t)(bb * kHeads + hh) * kSeq * kHd;
    const __half* Kp = g_k + (size_t)(bb * kHeads + hh) * kSeq * kHd;
    const __half* Vp = g_v + (size_t)(bb * kHeads + hh) * kSeq * kHd;

    const int kvRow = tid >> 1, kvHalf = tid & 1;

    // prologue: KV tile 0
    {
        const __half* ks = Kp + (size_t)kvRow * kHd + kvHalf * 32;
        const __half* vs = Vp + (size_t)kvRow * kHd + kvHalf * 32;
        const uint32_t dK = sQ + A_KV + kvRow * G_ROWB + kvHalf * 64;
        const uint32_t dV = dK + A_TILE;
#pragma unroll
        for (int j = 0; j < 4; j++) cp16(dK + j * 16, ks + j * 8);
#pragma unroll
        for (int j = 0; j < 4; j++) cp16(dV + j * 16, vs + j * 8);
        cp_commit();
    }

    // Stage Q (pre-scaled by 0.125 at QKV epilogue)
    {
        const __half* qr = Qp + (size_t)(q0 + tid) * kHd;
        char* qd = sm + tid * G_ROWB;
#pragma unroll
        for (int j = 0; j < 8; j++)
            *(uint4*)(qd + j * 16) = *(const uint4*)(qr + j * 8);
    }
    __syncthreads();

    const uint32_t lOff = (lane & 15) * G_ROWB + (lane >> 4) * 16;
    unsigned qf[4][2][4];
    {
        const uint32_t qBase = sQ + wq * G_ROWB + lOff;
#pragma unroll
        for (int ks = 0; ks < 4; ks++)
#pragma unroll
            for (int mt = 0; mt < 2; mt++)
                ldm_x4(qf[ks][mt][0], qf[ks][mt][1], qf[ks][mt][2], qf[ks][mt][3],
                       qBase + mt * 16 * G_ROWB + ks * 32);
    }

    float o[2][8][4];
#pragma unroll
    for (int mt = 0; mt < 2; mt++)
#pragma unroll
        for (int nt = 0; nt < 8; nt++)
#pragma unroll
            for (int i = 0; i < 4; i++) o[mt][nt][i] = 0.f;
    float mrun[2][2] = {{-1e30f, -1e30f}, {-1e30f, -1e30f}};
    float lrun[2][2] = {{0.f, 0.f}, {0.f, 0.f}};

    for (int t = 0; t < 16; t++) {
        if (t + 1 < 16) {
            const uint32_t base = sQ + A_KV + ((t + 1) & 1) * 2 * A_TILE;
            const __half* ks = Kp + (size_t)((t + 1) * 64 + kvRow) * kHd + kvHalf * 32;
            const __half* vs = Vp + (size_t)((t + 1) * 64 + kvRow) * kHd + kvHalf * 32;
            const uint32_t dK = base + kvRow * G_ROWB + kvHalf * 64;
            const uint32_t dV = dK + A_TILE;
#pragma unroll
            for (int j = 0; j < 4; j++) cp16(dK + j * 16, ks + j * 8);
#pragma unroll
            for (int j = 0; j < 4; j++) cp16(dV + j * 16, vs + j * 8);
            cp_commit();
            cp_wait<1>();
        } else {
            cp_wait<0>();
        }
        __syncthreads();

        const uint32_t kB = sQ + A_KV + (t & 1) * 2 * A_TILE;
        const uint32_t vB = kB + A_TILE;

        // S = Q K^T
        float s[2][8][4];
#pragma unroll
        for (int mt = 0; mt < 2; mt++)
#pragma unroll
            for (int nt = 0; nt < 8; nt++)
#pragma unroll
                for (int i = 0; i < 4; i++) s[mt][nt][i] = 0.f;

#pragma unroll
        for (int ks = 0; ks < 4; ks++) {
            unsigned bf[8][2];
#pragma unroll
            for (int np = 0; np < 4; np++) {
                unsigned r0, r1, r2, r3;
                ldm_x4(r0, r1, r2, r3, kB + np * 16 * G_ROWB + ks * 32 + lOff);
                bf[2 * np][0] = r0; bf[2 * np + 1][0] = r1;
                bf[2 * np][1] = r2; bf[2 * np + 1][1] = r3;
            }
#pragma unroll
            for (int mt = 0; mt < 2; mt++)
#pragma unroll
                for (int nt = 0; nt < 8; nt++)
                    mma_fp16(s[mt][nt], qf[ks][mt], bf[nt]);
        }

        // Online softmax
#pragma unroll
        for (int mt = 0; mt < 2; mt++) {
            float t0 = -1e30f, t1 = -1e30f;
#pragma unroll
            for (int nt = 0; nt < 8; nt++) {
                t0 = fmaxf(t0, fmaxf(s[mt][nt][0], s[mt][nt][1]));
                t1 = fmaxf(t1, fmaxf(s[mt][nt][2], s[mt][nt][3]));
            }
            t0 = qredmax(t0);
            t1 = qredmax(t1);
            const float mn0 = fmaxf(mrun[mt][0], t0);
            const float mn1 = fmaxf(mrun[mt][1], t1);
            const float a0 = __expf(mrun[mt][0] - mn0);
            const float a1 = __expf(mrun[mt][1] - mn1);
            float s0 = 0.f, s1 = 0.f;
#pragma unroll
            for (int nt = 0; nt < 8; nt++) {
                s[mt][nt][0] = __expf(s[mt][nt][0] - mn0); s0 += s[mt][nt][0];
                s[mt][nt][1] = __expf(s[mt][nt][1] - mn0); s0 += s[mt][nt][1];
                s[mt][nt][2] = __expf(s[mt][nt][2] - mn1); s1 += s[mt][nt][2];
                s[mt][nt][3] = __expf(s[mt][nt][3] - mn1); s1 += s[mt][nt][3];
            }
            lrun[mt][0] = lrun[mt][0] * a0 + qredsum(s0);
            lrun[mt][1] = lrun[mt][1] * a1 + qredsum(s1);
            mrun[mt][0] = mn0;
            mrun[mt][1] = mn1;
#pragma unroll
            for (int nt = 0; nt < 8; nt++) {
                o[mt][nt][0] *= a0; o[mt][nt][1] *= a0;
                o[mt][nt][2] *= a1; o[mt][nt][3] *= a1;
            }
        }

        // O += P V (register-resident P; V frags via ldmatrix.trans)
#pragma unroll
        for (int ks = 0; ks < 4; ks++) {
            unsigned pf[2][4];
#pragma unroll
            for (int mt = 0; mt < 2; mt++) {
                pf[mt][0] = h2u(s[mt][2 * ks    ][0], s[mt][2 * ks    ][1]);
                pf[mt][1] = h2u(s[mt][2 * ks    ][2], s[mt][2 * ks    ][3]);
                pf[mt][2] = h2u(s[mt][2 * ks + 1][0], s[mt][2 * ks + 1][1]);
                pf[mt][3] = h2u(s[mt][2 * ks + 1][2], s[mt][2 * ks + 1][3]);
            }
            unsigned vf[8][2];
#pragma unroll
            for (int np = 0; np < 4; np++) {
                unsigned r0, r1, r2, r3;
                ldm_x4_t(r0, r1, r2, r3,
                         vB + ks * 16 * G_ROWB + np * 32 + lOff);
                vf[2 * np][0] = r0; vf[2 * np][1] = r1;
                vf[2 * np + 1][0] = r2; vf[2 * np + 1][1] = r3;
            }
#pragma unroll
            for (int mt = 0; mt < 2; mt++)
#pragma unroll
                for (int nt = 0; nt < 8; nt++)
                    mma_fp16(o[mt][nt], pf[mt], vf[nt]);
        }
        __syncthreads();
    }

    // Epilogue: normalize, write att (half) as [b, n, h*64+d]
#pragma unroll
    for (int mt = 0; mt < 2; mt++) {
        const float inv0 = 1.f / lrun[mt][0], inv1 = 1.f / lrun[mt][1];
        const int r0 = q0 + wq + mt * 16 + tg;
        const int r1 = r0 + 8;
#pragma unroll
        for (int nt = 0; nt < 8; nt++) {
            const int dd = nt * 8 + 2 * tl;
            *(__half2*)&g_att[(size_t)(bb * kSeq + r0) * kDim + hh * kHd + dd] =
                __floats2half2_rn(o[mt][nt][0] * inv0, o[mt][nt][1] * inv0);
            *(__half2*)&g_att[(size_t)(bb * kSeq + r1) * kDim + hh * kHd + dd] =
                __floats2half2_rn(o[mt][nt][2] * inv1, o[mt][nt][3] * inv1);
        }
    }
}

// ---------------------------------------------------------------------------
extern "C" void kernel_launch(void* const* d_in, const int* in_sizes, int n_in,
                              void* d_out, int out_size) {
    (void)in_sizes; (void)n_in; (void)out_size;
    const float* x      = (const float*)d_in[0];
    const float* w_qkv  = (const float*)d_in[1];
    const float* w_proj = (const float*)d_in[2];
    const float* b_proj = (const float*)d_in[3];
    float* out = (float*)d_out;

    cudaFuncSetAttribute(gemm4<0>, cudaFuncAttributeMaxDynamicSharedMemorySize, SMEM_G);
    cudaFuncSetAttribute(gemm4<1>, cudaFuncAttributeMaxDynamicSharedMemorySize, SMEM_G);
    cudaFuncSetAttribute(attn2, cudaFuncAttributeMaxDynamicSharedMemorySize, SMEM_A);

    // 0) fp32 -> fp16
    cvt_kernel<<<(kBatch * kSeq * kDim / 4 + 255) / 256, 256>>>(x, 0,
        kBatch * kSeq * kDim / 4);
    cvt_kernel<<<(3 * kDim * kDim / 4 + 255) / 256, 256>>>(w_qkv, 1,
        3 * kDim * kDim / 4);
    cvt_kernel<<<(kDim * kDim / 4 + 255) / 256, 256>>>(w_proj, 2,
        kDim * kDim / 4);

    // 1) QKV projection: M=8192, N=3072 -> g_q (x0.125) / g_k / g_v
    gemm4<0><<<dim3(3 * kDim / 256, kBatch * kSeq / 128), 512, SMEM_G>>>(
        nullptr, nullptr);

    // 2) Flash attention: 8 q-tiles x 128 heads
    attn2<<<kBatch * kHeads * (kSeq / 128), 128, SMEM_A>>>();

    // 3) Output projection + bias: M=8192, N=1024 -> f32 out
    gemm4<1><<<dim3(kDim / 256, kBatch * kSeq / 128), 512, SMEM_G>>>(
        b_proj, out);
}